// round 6
// baseline (speedup 1.0000x reference)
#include <cuda_runtime.h>
#include <cuda_fp16.h>
#include <mma.h>
#include <math.h>

using namespace nvcuda;

#define NN 50000
#define NNP 50048
#define EE 1600000
#define VV 100000
#define DD 128
#define OO 64
#define TOT (NN*16)
#define NB 49   // ceil(NN/1024)

// ---------------- scratch (static device globals; no allocs allowed) ----------
__device__ int    g_cnt[NN];
__device__ int    g_offs[NN + 1];
__device__ int    g_csr[EE];
__device__ int    g_bsum[64];
__device__ float  g_isqrt[NN];
__device__ float  g_dinv[NN];
__device__ __half g_xh[NN * DD];    // embedding output (fp16)
__device__ __half g_hh[NNP * DD];   // relu(gemm1) (fp16)
__device__ __half g_zh[NN * OO];    // z (fp16)
__device__ __half g_w1h[DD * DD];   // W1 fp16
__device__ __half g_wabh[DD * DD];  // [Wmu|Wls] fp16

// ---------------- CSR build ---------------------------------------------------
__global__ void k_hist(const int* __restrict__ dst) {
    int base = (blockIdx.x * blockDim.x + threadIdx.x) * 8;
    if (base + 8 <= EE) {
        int4 d0 = *(const int4*)(dst + base);
        int4 d1 = *(const int4*)(dst + base + 4);
        atomicAdd(&g_cnt[d0.x], 1);
        atomicAdd(&g_cnt[d0.y], 1);
        atomicAdd(&g_cnt[d0.z], 1);
        atomicAdd(&g_cnt[d0.w], 1);
        atomicAdd(&g_cnt[d1.x], 1);
        atomicAdd(&g_cnt[d1.y], 1);
        atomicAdd(&g_cnt[d1.z], 1);
        atomicAdd(&g_cnt[d1.w], 1);
    } else {
        for (int e = base; e < EE; e++) atomicAdd(&g_cnt[dst[e]], 1);
    }
}

// level-1 scan: 49 blocks of 1024, local exclusive scan + block sums
__global__ __launch_bounds__(1024) void k_scan1() {
    __shared__ int s[1024];
    int t = threadIdx.x;
    int i = blockIdx.x * 1024 + t;
    int v = (i < NN) ? g_cnt[i] : 0;
    s[t] = v;
    __syncthreads();
    #pragma unroll
    for (int off = 1; off < 1024; off <<= 1) {
        int u = (t >= off) ? s[t - off] : 0;
        __syncthreads();
        s[t] += u;
        __syncthreads();
    }
    if (i < NN) g_offs[i] = s[t] - v;
    if (t == 1023) g_bsum[blockIdx.x] = s[1023];
}

// fixup: each block computes the (<=2) chunk prefixes it needs, then degree math
__global__ void k_scanfix() {
    __shared__ int pre[2];
    int c0 = (blockIdx.x * 256) >> 10;
    if (threadIdx.x < 2) {
        int c = c0 + threadIdx.x;
        int sum = 0;
        for (int q = 0; q < c && q < NB; q++) sum += g_bsum[q];
        pre[threadIdx.x] = sum;
    }
    __syncthreads();
    int i = blockIdx.x * 256 + threadIdx.x;
    if (i >= NN) return;
    g_offs[i] += pre[(i >> 10) - c0];
    int c = g_cnt[i];
    float deg = (float)(c + 1);
    g_isqrt[i] = rsqrtf(deg);
    g_dinv[i]  = 1.0f / deg;
    g_cnt[i]   = 0;
    if (i == 0) g_offs[NN] = EE;
}

__global__ void k_scatter(const int* __restrict__ src, const int* __restrict__ dst) {
    int base = (blockIdx.x * blockDim.x + threadIdx.x) * 4;
    if (base + 4 <= EE) {
        int4 d = *(const int4*)(dst + base);
        int4 s = *(const int4*)(src + base);
        int p0 = g_offs[d.x] + atomicAdd(&g_cnt[d.x], 1); g_csr[p0] = s.x;
        int p1 = g_offs[d.y] + atomicAdd(&g_cnt[d.y], 1); g_csr[p1] = s.y;
        int p2 = g_offs[d.z] + atomicAdd(&g_cnt[d.z], 1); g_csr[p2] = s.z;
        int p3 = g_offs[d.w] + atomicAdd(&g_cnt[d.w], 1); g_csr[p3] = s.w;
    } else {
        for (int e = base; e < EE; e++) {
            int d = dst[e];
            int pos = g_offs[d] + atomicAdd(&g_cnt[d], 1);
            g_csr[pos] = src[e];
        }
    }
}

// ---------------- weight fp16 conversion (single kernel) ----------------------
__global__ void k_cvt(const float* __restrict__ W1, const float* __restrict__ Wmu,
                      const float* __restrict__ Wls) {
    int i = blockIdx.x * 256 + threadIdx.x;
    if (i < DD * DD) {
        g_w1h[i] = __float2half(W1[i]);
    } else if (i < 2 * DD * DD) {
        int j = i - DD * DD;
        int r = j >> 7, cc = j & 127;
        g_wabh[j] = __float2half(cc < 64 ? Wmu[r * 64 + cc] : Wls[r * 64 + (cc - 64)]);
    }
}

// ---------------- EmbeddingBag(sum, weighted) + L2 normalize -> fp16 ----------
__global__ void k_embed(const int* __restrict__ fidx, const int* __restrict__ foff,
                        const float* __restrict__ fw, const float* __restrict__ emb) {
    int w = (blockIdx.x * blockDim.x + threadIdx.x) >> 5;
    int lane = threadIdx.x & 31;
    if (w >= NN) return;
    int start = foff[w];
    int end = (w + 1 < NN) ? foff[w + 1] : TOT;
    float4 acc = make_float4(0.f, 0.f, 0.f, 0.f);
    int k = start;
    for (; k + 4 <= end; k += 4) {
        int i0 = fidx[k], i1 = fidx[k+1], i2 = fidx[k+2], i3 = fidx[k+3];
        float w0 = fw[k], w1 = fw[k+1], w2 = fw[k+2], w3 = fw[k+3];
        float4 v0 = ((const float4*)emb)[i0 * 32 + lane];
        float4 v1 = ((const float4*)emb)[i1 * 32 + lane];
        float4 v2 = ((const float4*)emb)[i2 * 32 + lane];
        float4 v3 = ((const float4*)emb)[i3 * 32 + lane];
        acc.x = fmaf(w0, v0.x, fmaf(w1, v1.x, fmaf(w2, v2.x, fmaf(w3, v3.x, acc.x))));
        acc.y = fmaf(w0, v0.y, fmaf(w1, v1.y, fmaf(w2, v2.y, fmaf(w3, v3.y, acc.y))));
        acc.z = fmaf(w0, v0.z, fmaf(w1, v1.z, fmaf(w2, v2.z, fmaf(w3, v3.z, acc.z))));
        acc.w = fmaf(w0, v0.w, fmaf(w1, v1.w, fmaf(w2, v2.w, fmaf(w3, v3.w, acc.w))));
    }
    for (; k < end; k++) {
        int idx = fidx[k];
        float wt = fw[k];
        float4 v = ((const float4*)emb)[idx * 32 + lane];
        acc.x = fmaf(wt, v.x, acc.x);
        acc.y = fmaf(wt, v.y, acc.y);
        acc.z = fmaf(wt, v.z, acc.z);
        acc.w = fmaf(wt, v.w, acc.w);
    }
    float ss = acc.x * acc.x + acc.y * acc.y + acc.z * acc.z + acc.w * acc.w;
    for (int o = 16; o > 0; o >>= 1) ss += __shfl_xor_sync(0xffffffffu, ss, o);
    float inv = 1.0f / fmaxf(sqrtf(ss), 1e-12f);
    __half2 h0 = __floats2half2_rn(acc.x * inv, acc.y * inv);
    __half2 h1 = __floats2half2_rn(acc.z * inv, acc.w * inv);
    uint2 u;
    u.x = *(unsigned*)&h0;
    u.y = *(unsigned*)&h1;
    ((uint2*)g_xh)[w * 32 + lane] = u;
}

// ---------------- shared gather helper (agg one node into a uint2 of 4 halfs) --
__device__ __forceinline__ uint2 agg_node(const uint2* __restrict__ in2, int n, int lane) {
    int lo = g_offs[n], hi = g_offs[n + 1];
    float4 acc = make_float4(0.f, 0.f, 0.f, 0.f);
    int p = lo;
    for (; p + 8 <= hi; p += 8) {
        int j[8];
        float wj[8];
        uint2 u[8];
        #pragma unroll
        for (int q = 0; q < 8; q++) j[q] = g_csr[p + q];
        #pragma unroll
        for (int q = 0; q < 8; q++) wj[q] = g_isqrt[j[q]];
        #pragma unroll
        for (int q = 0; q < 8; q++) u[q] = in2[j[q] * 32 + lane];
        #pragma unroll
        for (int q = 0; q < 8; q++) {
            float2 f0 = __half22float2(*(__half2*)&u[q].x);
            float2 f1 = __half22float2(*(__half2*)&u[q].y);
            acc.x = fmaf(wj[q], f0.x, acc.x);
            acc.y = fmaf(wj[q], f0.y, acc.y);
            acc.z = fmaf(wj[q], f1.x, acc.z);
            acc.w = fmaf(wj[q], f1.y, acc.w);
        }
    }
    for (; p < hi; p++) {
        int jj = g_csr[p];
        float wj = g_isqrt[jj];
        uint2 u = in2[jj * 32 + lane];
        float2 f0 = __half22float2(*(__half2*)&u.x);
        float2 f1 = __half22float2(*(__half2*)&u.y);
        acc.x = fmaf(wj, f0.x, acc.x);
        acc.y = fmaf(wj, f0.y, acc.y);
        acc.z = fmaf(wj, f1.x, acc.z);
        acc.w = fmaf(wj, f1.y, acc.w);
    }
    float si = g_isqrt[n], di = g_dinv[n];
    uint2 us = in2[n * 32 + lane];
    float2 s0 = __half22float2(*(__half2*)&us.x);
    float2 s1 = __half22float2(*(__half2*)&us.y);
    __half2 h0 = __floats2half2_rn(acc.x * si + s0.x * di, acc.y * si + s0.y * di);
    __half2 h1 = __floats2half2_rn(acc.z * si + s1.x * di, acc.w * si + s1.y * di);
    uint2 r;
    r.x = *(unsigned*)&h0;
    r.y = *(unsigned*)&h1;
    return r;
}

// ---------------- fused agg + GEMM1: h = relu((A~ x) @ W1 + b1) -----------------
// 256 thr = 8 warps; tile = 128 rows. Phase1: each warp aggregates 16 nodes into
// smem A (fp16 128x128). Phase2: HMMA warp tile 32x64 from smem A, B from global.
__global__ __launch_bounds__(256) void k_ag1(const __half* __restrict__ in,
                                             const float* __restrict__ bias,
                                             __half* __restrict__ hout) {
    __shared__ __align__(16) char smraw[34816];
    __half (*sA)[128] = reinterpret_cast<__half(*)[128]>(smraw);
    float (*sC)[16][68] = reinterpret_cast<float(*)[16][68]>(smraw);

    int t = threadIdx.x;
    int w = t >> 5, lane = t & 31;
    int row0 = blockIdx.x * 128;
    const uint2* in2 = (const uint2*)in;

    #pragma unroll 1
    for (int s = 0; s < 16; s++) {
        int lr = w * 16 + s;
        int n = row0 + lr;
        uint2 u;
        if (n < NN) u = agg_node(in2, n, lane);
        else { u.x = 0u; u.y = 0u; }
        *(uint2*)&sA[lr][lane * 4] = u;
    }
    __syncthreads();

    int wr = w >> 1, wc = w & 1;
    int trow = wr * 32;
    int col0 = wc * 64;

    wmma::fragment<wmma::accumulator, 16, 16, 16, float> c[2][4];
    #pragma unroll
    for (int i = 0; i < 2; i++)
        #pragma unroll
        for (int j = 0; j < 4; j++) wmma::fill_fragment(c[i][j], 0.f);

    #pragma unroll
    for (int k0 = 0; k0 < 8; k0++) {
        wmma::fragment<wmma::matrix_a, 16, 16, 16, half, wmma::row_major> a[2];
        wmma::fragment<wmma::matrix_b, 16, 16, 16, half, wmma::row_major> b[4];
        #pragma unroll
        for (int i = 0; i < 2; i++)
            wmma::load_matrix_sync(a[i], &sA[trow + i * 16][k0 * 16], 128);
        #pragma unroll
        for (int j = 0; j < 4; j++)
            wmma::load_matrix_sync(b[j], g_w1h + (size_t)(k0 * 16) * 128 + col0 + j * 16, 128);
        #pragma unroll
        for (int i = 0; i < 2; i++)
            #pragma unroll
            for (int j = 0; j < 4; j++)
                wmma::mma_sync(c[i][j], a[i], b[j], c[i][j]);
    }
    __syncthreads();   // done reading sA; reuse as sC

    #pragma unroll
    for (int i = 0; i < 2; i++) {
        #pragma unroll
        for (int j = 0; j < 4; j++)
            wmma::store_matrix_sync(&sC[w][0][j * 16], c[i][j], 68, wmma::mem_row_major);
        __syncwarp();
        int r = lane >> 1, ch = (lane & 1) * 32;
        int gr = row0 + trow + i * 16 + r;
        if (gr < NN) {
            __align__(16) __half tmp[32];
            #pragma unroll
            for (int cc = 0; cc < 32; cc++) {
                float v = sC[w][r][ch + cc] + bias[col0 + ch + cc];
                tmp[cc] = __float2half(fmaxf(v, 0.f));
            }
            uint4* dstp = (uint4*)(hout + (size_t)gr * 128 + col0 + ch);
            const uint4* srcp = (const uint4*)tmp;
            #pragma unroll
            for (int q = 0; q < 4; q++) dstp[q] = srcp[q];
        }
        __syncwarp();
    }
}

// ---------------- fused agg + GEMM2 + z --------------------------------------
__global__ __launch_bounds__(256) void k_ag2z(const __half* __restrict__ in,
                                              const float* __restrict__ bmu,
                                              const float* __restrict__ bls,
                                              const float* __restrict__ noise) {
    __shared__ __align__(16) char smraw[34816];
    __half (*sA)[128] = reinterpret_cast<__half(*)[128]>(smraw);
    float (*sC)[16][132] = reinterpret_cast<float(*)[16][132]>(smraw);

    int t = threadIdx.x;
    int w = t >> 5, lane = t & 31;
    int row0 = blockIdx.x * 128;
    const uint2* in2 = (const uint2*)in;

    #pragma unroll 1
    for (int s = 0; s < 16; s++) {
        int lr = w * 16 + s;
        int n = row0 + lr;
        uint2 u;
        if (n < NN) u = agg_node(in2, n, lane);
        else { u.x = 0u; u.y = 0u; }
        *(uint2*)&sA[lr][lane * 4] = u;
    }
    __syncthreads();

    int wr = w >> 1, wc = w & 1;
    int trow = wr * 32;
    int col0 = wc * 64;

    wmma::fragment<wmma::accumulator, 16, 16, 16, float> c[2][4];
    #pragma unroll
    for (int i = 0; i < 2; i++)
        #pragma unroll
        for (int j = 0; j < 4; j++) wmma::fill_fragment(c[i][j], 0.f);

    #pragma unroll
    for (int k0 = 0; k0 < 8; k0++) {
        wmma::fragment<wmma::matrix_a, 16, 16, 16, half, wmma::row_major> a[2];
        wmma::fragment<wmma::matrix_b, 16, 16, 16, half, wmma::row_major> b[4];
        #pragma unroll
        for (int i = 0; i < 2; i++)
            wmma::load_matrix_sync(a[i], &sA[trow + i * 16][k0 * 16], 128);
        #pragma unroll
        for (int j = 0; j < 4; j++)
            wmma::load_matrix_sync(b[j], g_wabh + (size_t)(k0 * 16) * 128 + col0 + j * 16, 128);
        #pragma unroll
        for (int i = 0; i < 2; i++)
            #pragma unroll
            for (int j = 0; j < 4; j++)
                wmma::mma_sync(c[i][j], a[i], b[j], c[i][j]);
    }
    __syncthreads();   // done reading sA; reuse as sC

    #pragma unroll
    for (int i = 0; i < 2; i++) {
        #pragma unroll
        for (int j = 0; j < 4; j++)
            wmma::store_matrix_sync(&sC[wr][0][col0 + j * 16], c[i][j], 132, wmma::mem_row_major);
        __syncthreads();
        int tp = wc * 32 + lane;             // 0..63 within the warp-pair
        #pragma unroll 4
        for (int r = 0; r < 16; r++) {
            int gr = row0 + trow + i * 16 + r;
            if (gr < NN) {
                float mu = sC[wr][r][tp] + bmu[tp];
                float ls = sC[wr][r][64 + tp] + bls[tp];
                float zz = fmaf(noise[(size_t)gr * 64 + tp], expf(ls), mu);
                g_zh[(size_t)gr * 64 + tp] = __float2half(zz);
            }
        }
        __syncthreads();
    }
}

// ---------------- decoder + g_cnt re-zero for next replay ---------------------
__global__ void k_dec(const int* __restrict__ src, const int* __restrict__ dst,
                      float* __restrict__ out) {
    int gid = blockIdx.x * blockDim.x + threadIdx.x;
    if (gid < NN) g_cnt[gid] = 0;
    int g = blockIdx.x * (blockDim.x >> 3) + (threadIdx.x >> 3);
    int l = threadIdx.x & 7;
    if (g >= EE) return;
    int s = src[g], d = dst[g];
    uint4 ua = ((const uint4*)g_zh)[s * 8 + l];
    uint4 ub = ((const uint4*)g_zh)[d * 8 + l];
    float v = 0.f;
    const unsigned* pa = &ua.x;
    const unsigned* pb = &ub.x;
    #pragma unroll
    for (int q = 0; q < 4; q++) {
        float2 fa = __half22float2(*(const __half2*)&pa[q]);
        float2 fb = __half22float2(*(const __half2*)&pb[q]);
        v = fmaf(fa.x, fb.x, v);
        v = fmaf(fa.y, fb.y, v);
    }
    v += __shfl_xor_sync(0xffffffffu, v, 4);
    v += __shfl_xor_sync(0xffffffffu, v, 2);
    v += __shfl_xor_sync(0xffffffffu, v, 1);
    if (l == 0) out[g] = v;
}

// ---------------- launch -------------------------------------------------------
extern "C" void kernel_launch(void* const* d_in, const int* in_sizes, int n_in,
                              void* d_out, int out_size) {
    const int*   fidx  = (const int*)d_in[0];
    const int*   foff  = (const int*)d_in[1];
    const float* fw    = (const float*)d_in[2];
    const int*   edge  = (const int*)d_in[3];
    const float* noise = (const float*)d_in[4];
    const float* emb   = (const float*)d_in[5];
    const float* W1    = (const float*)d_in[6];
    const float* b1    = (const float*)d_in[7];
    const float* Wmu   = (const float*)d_in[8];
    const float* bmu   = (const float*)d_in[9];
    const float* Wls   = (const float*)d_in[10];
    const float* bls   = (const float*)d_in[11];
    float* out = (float*)d_out;

    const int* src = edge;
    const int* dst = edge + EE;

    __half *pxh = nullptr, *phh = nullptr;
    cudaGetSymbolAddress((void**)&pxh, g_xh);
    cudaGetSymbolAddress((void**)&phh, g_hh);

    static cudaStream_t s2 = nullptr;
    static cudaEvent_t evF = nullptr, evJ = nullptr;
    static bool ok = false;
    if (!s2) {
        ok = (cudaStreamCreateWithFlags(&s2, cudaStreamNonBlocking) == cudaSuccess) &&
             (cudaEventCreateWithFlags(&evF, cudaEventDisableTiming) == cudaSuccess) &&
             (cudaEventCreateWithFlags(&evJ, cudaEventDisableTiming) == cudaSuccess);
    }

    cudaStream_t se = ok ? s2 : 0;
    if (ok) {
        cudaEventRecord(evF, 0);
        cudaStreamWaitEvent(s2, evF, 0);
    }
    // branch B: weight conversion + embedding (independent of CSR build)
    k_cvt<<<(2 * DD * DD + 255) / 256, 256, 0, se>>>(W1, Wmu, Wls);
    k_embed<<<(NN + 3) / 4, 128, 0, se>>>(fidx, foff, fw, emb);
    if (ok) cudaEventRecord(evJ, s2);

    // branch A: CSR build (g_cnt is zero: init at load, re-zeroed by k_dec tail)
    k_hist<<<(EE / 8 + 255) / 256, 256>>>(dst);
    k_scan1<<<NB, 1024>>>();
    k_scanfix<<<(NN + 255) / 256, 256>>>();
    k_scatter<<<(EE / 4 + 255) / 256, 256>>>(src, dst);

    if (ok) cudaStreamWaitEvent(0, evJ, 0);

    k_ag1<<<(NN + 127) / 128, 256>>>(pxh, b1, phh);              // p1+gemm1 fused
    k_ag2z<<<(NN + 127) / 128, 256>>>(phh, bmu, bls, noise);     // p2+gemm2+z fused
    k_dec<<<(EE + 31) / 32, 256>>>(src, dst, out);
}

// round 7
// speedup vs baseline: 1.2542x; 1.2542x over previous
#include <cuda_runtime.h>
#include <cuda_fp16.h>
#include <math.h>

#define NN 50000
#define EE 1600000
#define VV 100000
#define DD 128
#define OO 64
#define TOT (NN*16)
#define NB 49   // ceil(NN/1024)

// ---------------- scratch (static device globals; no allocs allowed) ----------
__device__ int    g_cnt[NN];
__device__ int    g_offs[NN + 1];
__device__ int    g_csr[EE];
__device__ int    g_bsum[64];
__device__ float  g_isqrt[NN];
__device__ float  g_dinv[NN];
__device__ __half g_xh[NN * DD];    // embedding output (fp16)
__device__ __half g_ph[NN * DD];    // aggregation output (fp16, GEMM input)
__device__ __half g_hh[NN * DD];    // relu(gemm1) (fp16)
__device__ __half g_zh[NN * OO];    // z (fp16)

// ---------------- CSR build ---------------------------------------------------
__global__ void k_hist(const int* __restrict__ dst) {
    int base = (blockIdx.x * blockDim.x + threadIdx.x) * 8;
    if (base + 8 <= EE) {
        int4 d0 = *(const int4*)(dst + base);
        int4 d1 = *(const int4*)(dst + base + 4);
        atomicAdd(&g_cnt[d0.x], 1);
        atomicAdd(&g_cnt[d0.y], 1);
        atomicAdd(&g_cnt[d0.z], 1);
        atomicAdd(&g_cnt[d0.w], 1);
        atomicAdd(&g_cnt[d1.x], 1);
        atomicAdd(&g_cnt[d1.y], 1);
        atomicAdd(&g_cnt[d1.z], 1);
        atomicAdd(&g_cnt[d1.w], 1);
    } else {
        for (int e = base; e < EE; e++) atomicAdd(&g_cnt[dst[e]], 1);
    }
}

__global__ __launch_bounds__(1024) void k_scan1() {
    __shared__ int s[1024];
    int t = threadIdx.x;
    int i = blockIdx.x * 1024 + t;
    int v = (i < NN) ? g_cnt[i] : 0;
    s[t] = v;
    __syncthreads();
    #pragma unroll
    for (int off = 1; off < 1024; off <<= 1) {
        int u = (t >= off) ? s[t - off] : 0;
        __syncthreads();
        s[t] += u;
        __syncthreads();
    }
    if (i < NN) g_offs[i] = s[t] - v;
    if (t == 1023) g_bsum[blockIdx.x] = s[1023];
}

// fixup: each block computes the (<=2) chunk prefixes it spans, then degree math
__global__ void k_scanfix() {
    __shared__ int pre[2];
    int c0 = (blockIdx.x * 256) >> 10;
    if (threadIdx.x < 2) {
        int c = c0 + threadIdx.x;
        int sum = 0;
        for (int q = 0; q < c && q < NB; q++) sum += g_bsum[q];
        pre[threadIdx.x] = sum;
    }
    __syncthreads();
    int i = blockIdx.x * 256 + threadIdx.x;
    if (i >= NN) return;
    g_offs[i] += pre[(i >> 10) - c0];
    int c = g_cnt[i];
    float deg = (float)(c + 1);
    g_isqrt[i] = rsqrtf(deg);
    g_dinv[i]  = 1.0f / deg;
    g_cnt[i]   = 0;
    if (i == 0) g_offs[NN] = EE;
}

__global__ void k_scatter(const int* __restrict__ src, const int* __restrict__ dst) {
    int base = (blockIdx.x * blockDim.x + threadIdx.x) * 4;
    if (base + 4 <= EE) {
        int4 d = *(const int4*)(dst + base);
        int4 s = *(const int4*)(src + base);
        int p0 = g_offs[d.x] + atomicAdd(&g_cnt[d.x], 1); g_csr[p0] = s.x;
        int p1 = g_offs[d.y] + atomicAdd(&g_cnt[d.y], 1); g_csr[p1] = s.y;
        int p2 = g_offs[d.z] + atomicAdd(&g_cnt[d.z], 1); g_csr[p2] = s.z;
        int p3 = g_offs[d.w] + atomicAdd(&g_cnt[d.w], 1); g_csr[p3] = s.w;
    } else {
        for (int e = base; e < EE; e++) {
            int d = dst[e];
            int pos = g_offs[d] + atomicAdd(&g_cnt[d], 1);
            g_csr[pos] = src[e];
        }
    }
}

// ---------------- EmbeddingBag(sum, weighted) + L2 normalize -> fp16 ----------
__global__ void k_embed(const int* __restrict__ fidx, const int* __restrict__ foff,
                        const float* __restrict__ fw, const float* __restrict__ emb) {
    int w = (blockIdx.x * blockDim.x + threadIdx.x) >> 5;
    int lane = threadIdx.x & 31;
    if (w >= NN) return;
    int start = foff[w];
    int end = (w + 1 < NN) ? foff[w + 1] : TOT;
    float4 acc = make_float4(0.f, 0.f, 0.f, 0.f);
    int k = start;
    for (; k + 4 <= end; k += 4) {
        int i0 = fidx[k], i1 = fidx[k+1], i2 = fidx[k+2], i3 = fidx[k+3];
        float w0 = fw[k], w1 = fw[k+1], w2 = fw[k+2], w3 = fw[k+3];
        float4 v0 = ((const float4*)emb)[i0 * 32 + lane];
        float4 v1 = ((const float4*)emb)[i1 * 32 + lane];
        float4 v2 = ((const float4*)emb)[i2 * 32 + lane];
        float4 v3 = ((const float4*)emb)[i3 * 32 + lane];
        acc.x = fmaf(w0, v0.x, fmaf(w1, v1.x, fmaf(w2, v2.x, fmaf(w3, v3.x, acc.x))));
        acc.y = fmaf(w0, v0.y, fmaf(w1, v1.y, fmaf(w2, v2.y, fmaf(w3, v3.y, acc.y))));
        acc.z = fmaf(w0, v0.z, fmaf(w1, v1.z, fmaf(w2, v2.z, fmaf(w3, v3.z, acc.z))));
        acc.w = fmaf(w0, v0.w, fmaf(w1, v1.w, fmaf(w2, v2.w, fmaf(w3, v3.w, acc.w))));
    }
    for (; k < end; k++) {
        int idx = fidx[k];
        float wt = fw[k];
        float4 v = ((const float4*)emb)[idx * 32 + lane];
        acc.x = fmaf(wt, v.x, acc.x);
        acc.y = fmaf(wt, v.y, acc.y);
        acc.z = fmaf(wt, v.z, acc.z);
        acc.w = fmaf(wt, v.w, acc.w);
    }
    float ss = acc.x * acc.x + acc.y * acc.y + acc.z * acc.z + acc.w * acc.w;
    for (int o = 16; o > 0; o >>= 1) ss += __shfl_xor_sync(0xffffffffu, ss, o);
    float inv = 1.0f / fmaxf(sqrtf(ss), 1e-12f);
    __half2 h0 = __floats2half2_rn(acc.x * inv, acc.y * inv);
    __half2 h1 = __floats2half2_rn(acc.z * inv, acc.w * inv);
    uint2 u;
    u.x = *(unsigned*)&h0;
    u.y = *(unsigned*)&h1;
    ((uint2*)g_xh)[w * 32 + lane] = u;
}

// ---------------- GCN aggregation: fp16 gather, fp32 accumulate, fp16 out -----
__global__ void k_agg(const __half* __restrict__ in, __half* __restrict__ out) {
    int w = (blockIdx.x * blockDim.x + threadIdx.x) >> 5;
    int lane = threadIdx.x & 31;
    if (w >= NN) return;
    int lo = g_offs[w], hi = g_offs[w + 1];
    const uint2* in2 = (const uint2*)in;
    float4 acc = make_float4(0.f, 0.f, 0.f, 0.f);
    int p = lo;
    for (; p + 8 <= hi; p += 8) {
        int j[8];
        float wj[8];
        uint2 u[8];
        #pragma unroll
        for (int q = 0; q < 8; q++) j[q] = g_csr[p + q];
        #pragma unroll
        for (int q = 0; q < 8; q++) wj[q] = g_isqrt[j[q]];
        #pragma unroll
        for (int q = 0; q < 8; q++) u[q] = in2[j[q] * 32 + lane];
        #pragma unroll
        for (int q = 0; q < 8; q++) {
            float2 f0 = __half22float2(*(__half2*)&u[q].x);
            float2 f1 = __half22float2(*(__half2*)&u[q].y);
            acc.x = fmaf(wj[q], f0.x, acc.x);
            acc.y = fmaf(wj[q], f0.y, acc.y);
            acc.z = fmaf(wj[q], f1.x, acc.z);
            acc.w = fmaf(wj[q], f1.y, acc.w);
        }
    }
    for (; p < hi; p++) {
        int jj = g_csr[p];
        float wj = g_isqrt[jj];
        uint2 u = in2[jj * 32 + lane];
        float2 f0 = __half22float2(*(__half2*)&u.x);
        float2 f1 = __half22float2(*(__half2*)&u.y);
        acc.x = fmaf(wj, f0.x, acc.x);
        acc.y = fmaf(wj, f0.y, acc.y);
        acc.z = fmaf(wj, f1.x, acc.z);
        acc.w = fmaf(wj, f1.y, acc.w);
    }
    float si = g_isqrt[w], di = g_dinv[w];
    uint2 us = in2[w * 32 + lane];
    float2 s0 = __half22float2(*(__half2*)&us.x);
    float2 s1 = __half22float2(*(__half2*)&us.y);
    __half2 h0 = __floats2half2_rn(acc.x * si + s0.x * di, acc.y * si + s0.y * di);
    __half2 h1 = __floats2half2_rn(acc.z * si + s1.x * di, acc.w * si + s1.y * di);
    uint2 u;
    u.x = *(unsigned*)&h0;
    u.y = *(unsigned*)&h1;
    ((uint2*)out)[w * 32 + lane] = u;
}

// ---------------- GEMM1: h = relu(P @ W1 + b1), fp16 A, 128x128, 8x8 tile -----
__global__ __launch_bounds__(256) void k_gemm1(const __half* __restrict__ P,
                                               const float* __restrict__ W,
                                               const float* __restrict__ b,
                                               __half* __restrict__ hout) {
    __shared__ float smem_u[8320];              // sW[32][128] + sP[128][33]
    float (*sW)[128] = reinterpret_cast<float(*)[128]>(smem_u);
    float (*sP)[33]  = reinterpret_cast<float(*)[33]>(smem_u + 4096);

    int t = threadIdx.x;
    int row0 = blockIdx.x * 128;
    int tr = t >> 4, tc = t & 15;

    float acc[8][8];
    #pragma unroll
    for (int i = 0; i < 8; i++)
        #pragma unroll
        for (int j = 0; j < 8; j++) acc[i][j] = 0.f;

    for (int c = 0; c < 4; c++) {
        #pragma unroll
        for (int q = 0; q < 4; q++) {
            int e = t + q * 256;
            int kk = e >> 5, c4 = e & 31;
            ((float4*)&sW[kk][0])[c4] = ((const float4*)W)[(c * 32 + kk) * 32 + c4];
        }
        #pragma unroll
        for (int q = 0; q < 4; q++) {
            int e = t + q * 256;
            int r = e >> 3, c4 = e & 7;
            int gr = row0 + r;
            float2 f0 = make_float2(0.f, 0.f), f1 = make_float2(0.f, 0.f);
            if (gr < NN) {
                uint2 u = ((const uint2*)P)[gr * 32 + c * 8 + c4];
                f0 = __half22float2(*(__half2*)&u.x);
                f1 = __half22float2(*(__half2*)&u.y);
            }
            sP[r][c4 * 4 + 0] = f0.x;
            sP[r][c4 * 4 + 1] = f0.y;
            sP[r][c4 * 4 + 2] = f1.x;
            sP[r][c4 * 4 + 3] = f1.y;
        }
        __syncthreads();
        #pragma unroll 8
        for (int d = 0; d < 32; d++) {
            float a[8];
            #pragma unroll
            for (int r = 0; r < 8; r++) a[r] = sP[tr * 8 + r][d];
            float4 w0 = *(const float4*)&sW[d][tc * 8];
            float4 w1 = *(const float4*)&sW[d][tc * 8 + 4];
            float wv[8] = {w0.x, w0.y, w0.z, w0.w, w1.x, w1.y, w1.z, w1.w};
            #pragma unroll
            for (int r = 0; r < 8; r++)
                #pragma unroll
                for (int cc = 0; cc < 8; cc++)
                    acc[r][cc] = fmaf(a[r], wv[cc], acc[r][cc]);
        }
        __syncthreads();
    }

    float4 b0 = ((const float4*)b)[tc * 2];
    float4 b1 = ((const float4*)b)[tc * 2 + 1];
    float bv[8] = {b0.x, b0.y, b0.z, b0.w, b1.x, b1.y, b1.z, b1.w};
    #pragma unroll
    for (int r = 0; r < 8; r++) {
        int gr = row0 + tr * 8 + r;
        if (gr < NN) {
            float o[8];
            #pragma unroll
            for (int cc = 0; cc < 8; cc++) o[cc] = fmaxf(acc[r][cc] + bv[cc], 0.f);
            __half2 h0 = __floats2half2_rn(o[0], o[1]);
            __half2 h1 = __floats2half2_rn(o[2], o[3]);
            __half2 h2 = __floats2half2_rn(o[4], o[5]);
            __half2 h3 = __floats2half2_rn(o[6], o[7]);
            uint4 u;
            u.x = *(unsigned*)&h0; u.y = *(unsigned*)&h1;
            u.z = *(unsigned*)&h2; u.w = *(unsigned*)&h3;
            ((uint4*)hout)[gr * 16 + tc] = u;
        }
    }
}

// ---------------- GEMM2 + fused z -> fp16, fp16 A ------------------------------
__global__ __launch_bounds__(256) void k_gemm2z(const __half* __restrict__ P,
                                                const float* __restrict__ Wa,
                                                const float* __restrict__ Wb,
                                                const float* __restrict__ ba,
                                                const float* __restrict__ bb,
                                                const float* __restrict__ noise) {
    __shared__ float smem_u[8320];              // sW+sP, reused as sEx[128][65]
    float (*sW)[128] = reinterpret_cast<float(*)[128]>(smem_u);
    float (*sP)[33]  = reinterpret_cast<float(*)[33]>(smem_u + 4096);
    float (*sEx)[65] = reinterpret_cast<float(*)[65]>(smem_u);

    int t = threadIdx.x;
    int row0 = blockIdx.x * 128;
    int tr = t >> 4, tc = t & 15;

    float acc[8][8];
    #pragma unroll
    for (int i = 0; i < 8; i++)
        #pragma unroll
        for (int j = 0; j < 8; j++) acc[i][j] = 0.f;

    for (int c = 0; c < 4; c++) {
        #pragma unroll
        for (int q = 0; q < 4; q++) {
            int e = t + q * 256;
            int kk = e >> 5, c4 = e & 31;
            float4 v;
            if (c4 < 16) v = ((const float4*)Wa)[(c * 32 + kk) * 16 + c4];
            else         v = ((const float4*)Wb)[(c * 32 + kk) * 16 + (c4 - 16)];
            ((float4*)&sW[kk][0])[c4] = v;
        }
        #pragma unroll
        for (int q = 0; q < 4; q++) {
            int e = t + q * 256;
            int r = e >> 3, c4 = e & 7;
            int gr = row0 + r;
            float2 f0 = make_float2(0.f, 0.f), f1 = make_float2(0.f, 0.f);
            if (gr < NN) {
                uint2 u = ((const uint2*)P)[gr * 32 + c * 8 + c4];
                f0 = __half22float2(*(__half2*)&u.x);
                f1 = __half22float2(*(__half2*)&u.y);
            }
            sP[r][c4 * 4 + 0] = f0.x;
            sP[r][c4 * 4 + 1] = f0.y;
            sP[r][c4 * 4 + 2] = f1.x;
            sP[r][c4 * 4 + 3] = f1.y;
        }
        __syncthreads();
        #pragma unroll 8
        for (int d = 0; d < 32; d++) {
            float a[8];
            #pragma unroll
            for (int r = 0; r < 8; r++) a[r] = sP[tr * 8 + r][d];
            float4 w0 = *(const float4*)&sW[d][tc * 8];
            float4 w1 = *(const float4*)&sW[d][tc * 8 + 4];
            float wv[8] = {w0.x, w0.y, w0.z, w0.w, w1.x, w1.y, w1.z, w1.w};
            #pragma unroll
            for (int r = 0; r < 8; r++)
                #pragma unroll
                for (int cc = 0; cc < 8; cc++)
                    acc[r][cc] = fmaf(a[r], wv[cc], acc[r][cc]);
        }
        __syncthreads();
    }

    // ls threads (cols 64..127): sEx[lr][o] = exp(ls)*noise
    if (tc >= 8) {
        int ob = tc * 8 - 64;
        #pragma unroll
        for (int r = 0; r < 8; r++) {
            int lr = tr * 8 + r;
            int gr = row0 + lr;
            if (gr < NN) {
                float4 n0 = ((const float4*)(noise + gr * 64 + ob))[0];
                float4 n1 = ((const float4*)(noise + gr * 64 + ob))[1];
                float nv[8] = {n0.x, n0.y, n0.z, n0.w, n1.x, n1.y, n1.z, n1.w};
                #pragma unroll
                for (int cc = 0; cc < 8; cc++) {
                    float ls = acc[r][cc] + bb[ob + cc];
                    sEx[lr][ob + cc] = expf(ls) * nv[cc];
                }
            }
        }
    }
    __syncthreads();
    // mu threads (cols 0..63): z = mu + sEx -> fp16
    if (tc < 8) {
        int ob = tc * 8;
        #pragma unroll
        for (int r = 0; r < 8; r++) {
            int lr = tr * 8 + r;
            int gr = row0 + lr;
            if (gr < NN) {
                float o[8];
                #pragma unroll
                for (int cc = 0; cc < 8; cc++)
                    o[cc] = acc[r][cc] + ba[ob + cc] + sEx[lr][ob + cc];
                __half2 h0 = __floats2half2_rn(o[0], o[1]);
                __half2 h1 = __floats2half2_rn(o[2], o[3]);
                __half2 h2 = __floats2half2_rn(o[4], o[5]);
                __half2 h3 = __floats2half2_rn(o[6], o[7]);
                uint4 u;
                u.x = *(unsigned*)&h0; u.y = *(unsigned*)&h1;
                u.z = *(unsigned*)&h2; u.w = *(unsigned*)&h3;
                ((uint4*)g_zh)[gr * 8 + tc] = u;
            }
        }
    }
}

// ---------------- decoder + g_cnt re-zero for next replay ---------------------
__global__ void k_dec(const int* __restrict__ src, const int* __restrict__ dst,
                      float* __restrict__ out) {
    int gid = blockIdx.x * blockDim.x + threadIdx.x;
    if (gid < NN) g_cnt[gid] = 0;
    int g = blockIdx.x * (blockDim.x >> 3) + (threadIdx.x >> 3);
    int l = threadIdx.x & 7;
    if (g >= EE) return;
    int s = src[g], d = dst[g];
    uint4 ua = ((const uint4*)g_zh)[s * 8 + l];
    uint4 ub = ((const uint4*)g_zh)[d * 8 + l];
    float v = 0.f;
    const unsigned* pa = &ua.x;
    const unsigned* pb = &ub.x;
    #pragma unroll
    for (int q = 0; q < 4; q++) {
        float2 fa = __half22float2(*(const __half2*)&pa[q]);
        float2 fb = __half22float2(*(const __half2*)&pb[q]);
        v = fmaf(fa.x, fb.x, v);
        v = fmaf(fa.y, fb.y, v);
    }
    v += __shfl_xor_sync(0xffffffffu, v, 4);
    v += __shfl_xor_sync(0xffffffffu, v, 2);
    v += __shfl_xor_sync(0xffffffffu, v, 1);
    if (l == 0) out[g] = v;
}

// ---------------- launch -------------------------------------------------------
extern "C" void kernel_launch(void* const* d_in, const int* in_sizes, int n_in,
                              void* d_out, int out_size) {
    const int*   fidx  = (const int*)d_in[0];
    const int*   foff  = (const int*)d_in[1];
    const float* fw    = (const float*)d_in[2];
    const int*   edge  = (const int*)d_in[3];
    const float* noise = (const float*)d_in[4];
    const float* emb   = (const float*)d_in[5];
    const float* W1    = (const float*)d_in[6];
    const float* b1    = (const float*)d_in[7];
    const float* Wmu   = (const float*)d_in[8];
    const float* bmu   = (const float*)d_in[9];
    const float* Wls   = (const float*)d_in[10];
    const float* bls   = (const float*)d_in[11];
    float* out = (float*)d_out;

    const int* src = edge;
    const int* dst = edge + EE;

    __half *pxh = nullptr, *pph = nullptr, *phh = nullptr;
    cudaGetSymbolAddress((void**)&pxh, g_xh);
    cudaGetSymbolAddress((void**)&pph, g_ph);
    cudaGetSymbolAddress((void**)&phh, g_hh);

    static cudaStream_t s2 = nullptr;
    static cudaEvent_t evF = nullptr, evJ = nullptr;
    static bool ok = false;
    if (!s2) {
        ok = (cudaStreamCreateWithFlags(&s2, cudaStreamNonBlocking) == cudaSuccess) &&
             (cudaEventCreateWithFlags(&evF, cudaEventDisableTiming) == cudaSuccess) &&
             (cudaEventCreateWithFlags(&evJ, cudaEventDisableTiming) == cudaSuccess);
    }

    cudaStream_t se = ok ? s2 : 0;
    if (ok) {
        cudaEventRecord(evF, 0);
        cudaStreamWaitEvent(s2, evF, 0);
    }
    // branch B: embedding (independent of CSR build)
    k_embed<<<(NN + 3) / 4, 128, 0, se>>>(fidx, foff, fw, emb);
    if (ok) cudaEventRecord(evJ, s2);

    // branch A: CSR build (g_cnt zero at load; re-zeroed by k_dec tail each replay)
    k_hist<<<(EE / 8 + 255) / 256, 256>>>(dst);
    k_scan1<<<NB, 1024>>>();
    k_scanfix<<<(NN + 255) / 256, 256>>>();
    k_scatter<<<(EE / 4 + 255) / 256, 256>>>(src, dst);

    if (ok) cudaStreamWaitEvent(0, evJ, 0);

    k_agg<<<(NN + 3) / 4, 128>>>(pxh, pph);                        // p1 (fp16)
    k_gemm1<<<(NN + 127) / 128, 256>>>(pph, W1, b1, phh);          // h (fp16)
    k_agg<<<(NN + 3) / 4, 128>>>(phh, pph);                        // p2 (fp16)
    k_gemm2z<<<(NN + 127) / 128, 256>>>(pph, Wmu, Wls, bmu, bls, noise);
    k_dec<<<(EE + 31) / 32, 256>>>(src, dst, out);
}

// round 8
// speedup vs baseline: 1.3504x; 1.0767x over previous
#include <cuda_runtime.h>
#include <cuda_fp16.h>
#include <mma.h>
#include <math.h>

using namespace nvcuda;

#define NN 50000
#define EE 1600000
#define VV 100000
#define DD 128
#define OO 64
#define TOT (NN*16)
#define NB 49   // ceil(NN/1024)

// ---------------- scratch (static device globals; no allocs allowed) ----------
__device__ int    g_cnt[NN];
__device__ int    g_offs[NN + 1];
__device__ int2   g_csr2[EE];       // (src, eid) sorted by dst
__device__ int    g_bsum[64];
__device__ float  g_isqrt[NN];
__device__ float  g_dinv[NN];
__device__ __half g_xh[NN * DD];    // embedding output (fp16)
__device__ __half g_ph[NN * DD];    // aggregation output (fp16, GEMM A operand)
__device__ __half g_hh[NN * DD];    // relu(gemm1) (fp16)
__device__ __half g_zh[NN * OO];    // z (fp16)
__device__ __half g_w1h[DD * DD];   // W1 fp16
__device__ __half g_wabh[DD * DD];  // [Wmu|Wls] fp16

// ---------------- CSR build ---------------------------------------------------
__global__ void k_hist(const int* __restrict__ dst) {
    int base = (blockIdx.x * blockDim.x + threadIdx.x) * 8;
    if (base + 8 <= EE) {
        int4 d0 = *(const int4*)(dst + base);
        int4 d1 = *(const int4*)(dst + base + 4);
        atomicAdd(&g_cnt[d0.x], 1);
        atomicAdd(&g_cnt[d0.y], 1);
        atomicAdd(&g_cnt[d0.z], 1);
        atomicAdd(&g_cnt[d0.w], 1);
        atomicAdd(&g_cnt[d1.x], 1);
        atomicAdd(&g_cnt[d1.y], 1);
        atomicAdd(&g_cnt[d1.z], 1);
        atomicAdd(&g_cnt[d1.w], 1);
    } else {
        for (int e = base; e < EE; e++) atomicAdd(&g_cnt[dst[e]], 1);
    }
}

__global__ __launch_bounds__(1024) void k_scan1() {
    __shared__ int s[1024];
    int t = threadIdx.x;
    int i = blockIdx.x * 1024 + t;
    int v = (i < NN) ? g_cnt[i] : 0;
    s[t] = v;
    __syncthreads();
    #pragma unroll
    for (int off = 1; off < 1024; off <<= 1) {
        int u = (t >= off) ? s[t - off] : 0;
        __syncthreads();
        s[t] += u;
        __syncthreads();
    }
    if (i < NN) g_offs[i] = s[t] - v;
    if (t == 1023) g_bsum[blockIdx.x] = s[1023];
}

__global__ void k_scanfix() {
    __shared__ int pre[2];
    int c0 = (blockIdx.x * 256) >> 10;
    if (threadIdx.x < 2) {
        int c = c0 + threadIdx.x;
        int sum = 0;
        for (int q = 0; q < c && q < NB; q++) sum += g_bsum[q];
        pre[threadIdx.x] = sum;
    }
    __syncthreads();
    int i = blockIdx.x * 256 + threadIdx.x;
    if (i >= NN) return;
    g_offs[i] += pre[(i >> 10) - c0];
    int c = g_cnt[i];
    float deg = (float)(c + 1);
    g_isqrt[i] = rsqrtf(deg);
    g_dinv[i]  = 1.0f / deg;
    g_cnt[i]   = 0;
    if (i == 0) g_offs[NN] = EE;
}

__global__ void k_scatter(const int* __restrict__ src, const int* __restrict__ dst) {
    int base = (blockIdx.x * blockDim.x + threadIdx.x) * 4;
    if (base + 4 <= EE) {
        int4 d = *(const int4*)(dst + base);
        int4 s = *(const int4*)(src + base);
        int p0 = g_offs[d.x] + atomicAdd(&g_cnt[d.x], 1); g_csr2[p0] = make_int2(s.x, base);
        int p1 = g_offs[d.y] + atomicAdd(&g_cnt[d.y], 1); g_csr2[p1] = make_int2(s.y, base + 1);
        int p2 = g_offs[d.z] + atomicAdd(&g_cnt[d.z], 1); g_csr2[p2] = make_int2(s.z, base + 2);
        int p3 = g_offs[d.w] + atomicAdd(&g_cnt[d.w], 1); g_csr2[p3] = make_int2(s.w, base + 3);
    } else {
        for (int e = base; e < EE; e++) {
            int d = dst[e];
            int pos = g_offs[d] + atomicAdd(&g_cnt[d], 1);
            g_csr2[pos] = make_int2(src[e], e);
        }
    }
}

// ---------------- weight fp16 conversion (side stream) -------------------------
__global__ void k_cvt(const float* __restrict__ W1, const float* __restrict__ Wmu,
                      const float* __restrict__ Wls) {
    int i = blockIdx.x * 256 + threadIdx.x;
    if (i < DD * DD) {
        g_w1h[i] = __float2half(W1[i]);
    } else if (i < 2 * DD * DD) {
        int j = i - DD * DD;
        int r = j >> 7, cc = j & 127;
        g_wabh[j] = __float2half(cc < 64 ? Wmu[r * 64 + cc] : Wls[r * 64 + (cc - 64)]);
    }
}

// ---------------- EmbeddingBag(sum, weighted) + L2 normalize -> fp16 ----------
__global__ void k_embed(const int* __restrict__ fidx, const int* __restrict__ foff,
                        const float* __restrict__ fw, const float* __restrict__ emb) {
    int w = (blockIdx.x * blockDim.x + threadIdx.x) >> 5;
    int lane = threadIdx.x & 31;
    if (w >= NN) return;
    int start = foff[w];
    int end = (w + 1 < NN) ? foff[w + 1] : TOT;
    float4 acc = make_float4(0.f, 0.f, 0.f, 0.f);
    int k = start;
    for (; k + 4 <= end; k += 4) {
        int i0 = fidx[k], i1 = fidx[k+1], i2 = fidx[k+2], i3 = fidx[k+3];
        float w0 = fw[k], w1 = fw[k+1], w2 = fw[k+2], w3 = fw[k+3];
        float4 v0 = ((const float4*)emb)[i0 * 32 + lane];
        float4 v1 = ((const float4*)emb)[i1 * 32 + lane];
        float4 v2 = ((const float4*)emb)[i2 * 32 + lane];
        float4 v3 = ((const float4*)emb)[i3 * 32 + lane];
        acc.x = fmaf(w0, v0.x, fmaf(w1, v1.x, fmaf(w2, v2.x, fmaf(w3, v3.x, acc.x))));
        acc.y = fmaf(w0, v0.y, fmaf(w1, v1.y, fmaf(w2, v2.y, fmaf(w3, v3.y, acc.y))));
        acc.z = fmaf(w0, v0.z, fmaf(w1, v1.z, fmaf(w2, v2.z, fmaf(w3, v3.z, acc.z))));
        acc.w = fmaf(w0, v0.w, fmaf(w1, v1.w, fmaf(w2, v2.w, fmaf(w3, v3.w, acc.w))));
    }
    for (; k < end; k++) {
        int idx = fidx[k];
        float wt = fw[k];
        float4 v = ((const float4*)emb)[idx * 32 + lane];
        acc.x = fmaf(wt, v.x, acc.x);
        acc.y = fmaf(wt, v.y, acc.y);
        acc.z = fmaf(wt, v.z, acc.z);
        acc.w = fmaf(wt, v.w, acc.w);
    }
    float ss = acc.x * acc.x + acc.y * acc.y + acc.z * acc.z + acc.w * acc.w;
    for (int o = 16; o > 0; o >>= 1) ss += __shfl_xor_sync(0xffffffffu, ss, o);
    float inv = 1.0f / fmaxf(sqrtf(ss), 1e-12f);
    __half2 h0 = __floats2half2_rn(acc.x * inv, acc.y * inv);
    __half2 h1 = __floats2half2_rn(acc.z * inv, acc.w * inv);
    uint2 u;
    u.x = *(unsigned*)&h0;
    u.y = *(unsigned*)&h1;
    ((uint2*)g_xh)[w * 32 + lane] = u;
}

// ---------------- GCN aggregation: fp16 gather, fp32 accumulate, fp16 out -----
__global__ void k_agg(const __half* __restrict__ in, __half* __restrict__ out) {
    int w = (blockIdx.x * blockDim.x + threadIdx.x) >> 5;
    int lane = threadIdx.x & 31;
    if (w >= NN) return;
    int lo = g_offs[w], hi = g_offs[w + 1];
    const uint2* in2 = (const uint2*)in;
    float4 acc = make_float4(0.f, 0.f, 0.f, 0.f);
    int p = lo;
    for (; p + 8 <= hi; p += 8) {
        int j[8];
        float wj[8];
        uint2 u[8];
        #pragma unroll
        for (int q = 0; q < 8; q++) j[q] = g_csr2[p + q].x;
        #pragma unroll
        for (int q = 0; q < 8; q++) wj[q] = g_isqrt[j[q]];
        #pragma unroll
        for (int q = 0; q < 8; q++) u[q] = in2[j[q] * 32 + lane];
        #pragma unroll
        for (int q = 0; q < 8; q++) {
            float2 f0 = __half22float2(*(__half2*)&u[q].x);
            float2 f1 = __half22float2(*(__half2*)&u[q].y);
            acc.x = fmaf(wj[q], f0.x, acc.x);
            acc.y = fmaf(wj[q], f0.y, acc.y);
            acc.z = fmaf(wj[q], f1.x, acc.z);
            acc.w = fmaf(wj[q], f1.y, acc.w);
        }
    }
    for (; p < hi; p++) {
        int jj = g_csr2[p].x;
        float wj = g_isqrt[jj];
        uint2 u = in2[jj * 32 + lane];
        float2 f0 = __half22float2(*(__half2*)&u.x);
        float2 f1 = __half22float2(*(__half2*)&u.y);
        acc.x = fmaf(wj, f0.x, acc.x);
        acc.y = fmaf(wj, f0.y, acc.y);
        acc.z = fmaf(wj, f1.x, acc.z);
        acc.w = fmaf(wj, f1.y, acc.w);
    }
    float si = g_isqrt[w], di = g_dinv[w];
    uint2 us = in2[w * 32 + lane];
    float2 s0 = __half22float2(*(__half2*)&us.x);
    float2 s1 = __half22float2(*(__half2*)&us.y);
    __half2 h0 = __floats2half2_rn(acc.x * si + s0.x * di, acc.y * si + s0.y * di);
    __half2 h1 = __floats2half2_rn(acc.z * si + s1.x * di, acc.w * si + s1.y * di);
    uint2 u;
    u.x = *(unsigned*)&h0;
    u.y = *(unsigned*)&h1;
    ((uint2*)out)[w * 32 + lane] = u;
}

// ---------------- GEMM1 (HMMA, smem-staged): h = relu(A @ W1 + b1) -> fp16 ----
// 64-row tile, 8 warps (4 wr x 2 wc), warp tile 16x64, A+B staged in 48KB smem
__global__ __launch_bounds__(256) void k_gemm1w(const __half* __restrict__ A,
                                                const float* __restrict__ bias,
                                                __half* __restrict__ hout) {
    __shared__ __align__(32) char smraw[49152];
    __half* sA = (__half*)smraw;                       // 64x128 = 16KB
    __half* sB = (__half*)(smraw + 16384);             // 128x128 = 32KB
    float (*sC)[16][68] = reinterpret_cast<float(*)[16][68]>(smraw);  // overlay

    int t = threadIdx.x;
    int row0 = blockIdx.x * 64;

    // stage A (zero-pad tail rows) and B
    #pragma unroll
    for (int q = 0; q < 4; q++) {
        int idx = t + q * 256;                 // uint4 idx over 64x16
        int r = idx >> 4, c4 = idx & 15;
        int gr = row0 + r;
        uint4 v = make_uint4(0u, 0u, 0u, 0u);
        if (gr < NN) v = ((const uint4*)A)[gr * 16 + c4];
        ((uint4*)sA)[idx] = v;
    }
    #pragma unroll
    for (int q = 0; q < 8; q++) {
        int idx = t + q * 256;                 // uint4 idx over 128x16
        ((uint4*)sB)[idx] = ((const uint4*)g_w1h)[idx];
    }
    __syncthreads();

    int w = t >> 5, lane = t & 31;
    int wr = w >> 1, wc = w & 1;

    wmma::fragment<wmma::accumulator, 16, 16, 16, float> c[4];
    #pragma unroll
    for (int j = 0; j < 4; j++) wmma::fill_fragment(c[j], 0.f);

    #pragma unroll
    for (int k0 = 0; k0 < 8; k0++) {
        wmma::fragment<wmma::matrix_a, 16, 16, 16, half, wmma::row_major> a;
        wmma::load_matrix_sync(a, sA + (wr * 16) * 128 + k0 * 16, 128);
        #pragma unroll
        for (int j = 0; j < 4; j++) {
            wmma::fragment<wmma::matrix_b, 16, 16, 16, half, wmma::row_major> b;
            wmma::load_matrix_sync(b, sB + (k0 * 16) * 128 + wc * 64 + j * 16, 128);
            wmma::mma_sync(c[j], a, b, c[j]);
        }
    }
    __syncthreads();   // done with sA/sB; reuse as sC

    #pragma unroll
    for (int j = 0; j < 4; j++)
        wmma::store_matrix_sync(&sC[w][0][j * 16], c[j], 68, wmma::mem_row_major);
    __syncwarp();
    int r = lane >> 1, ch = (lane & 1) * 32;
    int gr = row0 + wr * 16 + r;
    int col0 = wc * 64;
    if (gr < NN) {
        __align__(16) __half tmp[32];
        #pragma unroll
        for (int cc = 0; cc < 32; cc++) {
            float v = sC[w][r][ch + cc] + bias[col0 + ch + cc];
            tmp[cc] = __float2half(fmaxf(v, 0.f));
        }
        uint4* dstp = (uint4*)(hout + (size_t)gr * 128 + col0 + ch);
        const uint4* srcp = (const uint4*)tmp;
        #pragma unroll
        for (int q = 0; q < 4; q++) dstp[q] = srcp[q];
    }
}

// ---------------- GEMM2 (HMMA, smem-staged) + fused z -> fp16 -------------------
__global__ __launch_bounds__(256) void k_gemm2zw(const __half* __restrict__ A,
                                                 const float* __restrict__ bmu,
                                                 const float* __restrict__ bls,
                                                 const float* __restrict__ noise) {
    __shared__ __align__(32) char smraw[49152];
    __half* sA = (__half*)smraw;
    __half* sB = (__half*)(smraw + 16384);
    float (*sC)[16][132] = reinterpret_cast<float(*)[16][132]>(smraw);  // 33792B

    int t = threadIdx.x;
    int row0 = blockIdx.x * 64;

    #pragma unroll
    for (int q = 0; q < 4; q++) {
        int idx = t + q * 256;
        int r = idx >> 4, c4 = idx & 15;
        int gr = row0 + r;
        uint4 v = make_uint4(0u, 0u, 0u, 0u);
        if (gr < NN) v = ((const uint4*)A)[gr * 16 + c4];
        ((uint4*)sA)[idx] = v;
    }
    #pragma unroll
    for (int q = 0; q < 8; q++) {
        int idx = t + q * 256;
        ((uint4*)sB)[idx] = ((const uint4*)g_wabh)[idx];
    }
    __syncthreads();

    int w = t >> 5, lane = t & 31;
    int wr = w >> 1, wc = w & 1;

    wmma::fragment<wmma::accumulator, 16, 16, 16, float> c[4];
    #pragma unroll
    for (int j = 0; j < 4; j++) wmma::fill_fragment(c[j], 0.f);

    #pragma unroll
    for (int k0 = 0; k0 < 8; k0++) {
        wmma::fragment<wmma::matrix_a, 16, 16, 16, half, wmma::row_major> a;
        wmma::load_matrix_sync(a, sA + (wr * 16) * 128 + k0 * 16, 128);
        #pragma unroll
        for (int j = 0; j < 4; j++) {
            wmma::fragment<wmma::matrix_b, 16, 16, 16, half, wmma::row_major> b;
            wmma::load_matrix_sync(b, sB + (k0 * 16) * 128 + wc * 64 + j * 16, 128);
            wmma::mma_sync(c[j], a, b, c[j]);
        }
    }
    __syncthreads();   // reuse smem as sC

    #pragma unroll
    for (int j = 0; j < 4; j++)
        wmma::store_matrix_sync(&sC[wr][0][wc * 64 + j * 16], c[j], 132, wmma::mem_row_major);
    __syncthreads();

    int tp = wc * 32 + lane;     // 0..63: output column handled by this thread
    #pragma unroll 4
    for (int r = 0; r < 16; r++) {
        int gr = row0 + wr * 16 + r;
        if (gr < NN) {
            float mu = sC[wr][r][tp] + bmu[tp];
            float ls = sC[wr][r][64 + tp] + bls[tp];
            float zz = fmaf(noise[(size_t)gr * 64 + tp], expf(ls), mu);
            g_zh[(size_t)gr * 64 + tp] = __float2half(zz);
        }
    }
}

// ---------------- decoder (CSR-ordered): one warp per dst node -----------------
// dst z row loaded once; 4 edges in flight per warp (8 lanes each); out[eid] scatter
__global__ void k_dec(float* __restrict__ out) {
    int gid = blockIdx.x * blockDim.x + threadIdx.x;
    if (gid < NN) g_cnt[gid] = 0;            // re-zero for next replay
    int n = gid >> 5;
    if (n >= NN) return;
    int lane = threadIdx.x & 31;
    int g = lane >> 3, sl = lane & 7;
    unsigned gm = 0xffu << (g * 8);

    int lo = g_offs[n], hi = g_offs[n + 1];
    uint4 zd = ((const uint4*)g_zh)[n * 8 + sl];
    float2 d0 = __half22float2(*(__half2*)&zd.x);
    float2 d1 = __half22float2(*(__half2*)&zd.y);
    float2 d2 = __half22float2(*(__half2*)&zd.z);
    float2 d3 = __half22float2(*(__half2*)&zd.w);

    for (int p = lo + g; p < hi; p += 4) {
        int2 e = g_csr2[p];
        uint4 za = ((const uint4*)g_zh)[e.x * 8 + sl];
        float2 a0 = __half22float2(*(__half2*)&za.x);
        float2 a1 = __half22float2(*(__half2*)&za.y);
        float2 a2 = __half22float2(*(__half2*)&za.z);
        float2 a3 = __half22float2(*(__half2*)&za.w);
        float v = a0.x * d0.x + a0.y * d0.y + a1.x * d1.x + a1.y * d1.y
                + a2.x * d2.x + a2.y * d2.y + a3.x * d3.x + a3.y * d3.y;
        v += __shfl_xor_sync(gm, v, 4);
        v += __shfl_xor_sync(gm, v, 2);
        v += __shfl_xor_sync(gm, v, 1);
        if (sl == 0) out[e.y] = v;
    }
}

// ---------------- launch -------------------------------------------------------
extern "C" void kernel_launch(void* const* d_in, const int* in_sizes, int n_in,
                              void* d_out, int out_size) {
    const int*   fidx  = (const int*)d_in[0];
    const int*   foff  = (const int*)d_in[1];
    const float* fw    = (const float*)d_in[2];
    const int*   edge  = (const int*)d_in[3];
    const float* noise = (const float*)d_in[4];
    const float* emb   = (const float*)d_in[5];
    const float* W1    = (const float*)d_in[6];
    const float* b1    = (const float*)d_in[7];
    const float* Wmu   = (const float*)d_in[8];
    const float* bmu   = (const float*)d_in[9];
    const float* Wls   = (const float*)d_in[10];
    const float* bls   = (const float*)d_in[11];
    float* out = (float*)d_out;

    const int* src = edge;
    const int* dst = edge + EE;

    __half *pxh = nullptr, *pph = nullptr, *phh = nullptr;
    cudaGetSymbolAddress((void**)&pxh, g_xh);
    cudaGetSymbolAddress((void**)&pph, g_ph);
    cudaGetSymbolAddress((void**)&phh, g_hh);

    static cudaStream_t s2 = nullptr;
    static cudaEvent_t evF = nullptr, evJ = nullptr;
    static bool ok = false;
    if (!s2) {
        ok = (cudaStreamCreateWithFlags(&s2, cudaStreamNonBlocking) == cudaSuccess) &&
             (cudaEventCreateWithFlags(&evF, cudaEventDisableTiming) == cudaSuccess) &&
             (cudaEventCreateWithFlags(&evJ, cudaEventDisableTiming) == cudaSuccess);
    }

    cudaStream_t se = ok ? s2 : 0;
    if (ok) {
        cudaEventRecord(evF, 0);
        cudaStreamWaitEvent(s2, evF, 0);
    }
    // branch B: weight conversion + embedding (independent of CSR build)
    k_cvt<<<(2 * DD * DD + 255) / 256, 256, 0, se>>>(W1, Wmu, Wls);
    k_embed<<<(NN + 3) / 4, 128, 0, se>>>(fidx, foff, fw, emb);
    if (ok) cudaEventRecord(evJ, s2);

    // branch A: CSR build (g_cnt zero at load; re-zeroed by k_dec tail each replay)
    k_hist<<<(EE / 8 + 255) / 256, 256>>>(dst);
    k_scan1<<<NB, 1024>>>();
    k_scanfix<<<(NN + 255) / 256, 256>>>();
    k_scatter<<<(EE / 4 + 255) / 256, 256>>>(src, dst);

    if (ok) cudaStreamWaitEvent(0, evJ, 0);

    k_agg<<<(NN + 3) / 4, 128>>>(pxh, pph);                       // p1 (fp16)
    k_gemm1w<<<(NN + 63) / 64, 256>>>(pph, b1, phh);              // h (HMMA)
    k_agg<<<(NN + 3) / 4, 128>>>(phh, pph);                       // p2 (fp16)
    k_gemm2zw<<<(NN + 63) / 64, 256>>>(pph, bmu, bls, noise);     // z (HMMA fused)
    k_dec<<<(NN * 32 + 255) / 256, 256>>>(out);
}

// round 9
// speedup vs baseline: 1.3613x; 1.0080x over previous
#include <cuda_runtime.h>
#include <cuda_fp16.h>
#include <mma.h>
#include <math.h>

using namespace nvcuda;

#define NN 50000
#define EE 1600000
#define VV 100000
#define DD 128
#define OO 64
#define TOT (NN*16)
#define NB 49   // ceil(NN/1024)

// ---------------- scratch (static device globals; no allocs allowed) ----------
__device__ int    g_cnt[NN];
__device__ int    g_offs[NN + 1];
__device__ int    g_csrs[EE];       // src sorted by dst
__device__ int    g_csre[EE];       // eid sorted by dst
__device__ int    g_bsum[64];
__device__ float  g_isqrt[NN];
__device__ float  g_dinv[NN];
__device__ __half g_xh[NN * DD];    // embedding output (fp16)
__device__ __half g_y[NN * DD];     // GEMM output (pre-aggregation), reused
__device__ __half g_hh[NN * DD];    // relu layer-1 output (fp16)
__device__ __half g_zh[NN * OO];    // z (fp16)
__device__ __half g_w1h[DD * DD];   // W1 fp16
__device__ __half g_wabh[DD * DD];  // [Wmu|Wls] fp16

// ---------------- CSR build ---------------------------------------------------
__global__ void k_hist(const int* __restrict__ dst) {
    int base = (blockIdx.x * blockDim.x + threadIdx.x) * 8;
    if (base + 8 <= EE) {
        int4 d0 = *(const int4*)(dst + base);
        int4 d1 = *(const int4*)(dst + base + 4);
        atomicAdd(&g_cnt[d0.x], 1);
        atomicAdd(&g_cnt[d0.y], 1);
        atomicAdd(&g_cnt[d0.z], 1);
        atomicAdd(&g_cnt[d0.w], 1);
        atomicAdd(&g_cnt[d1.x], 1);
        atomicAdd(&g_cnt[d1.y], 1);
        atomicAdd(&g_cnt[d1.z], 1);
        atomicAdd(&g_cnt[d1.w], 1);
    } else {
        for (int e = base; e < EE; e++) atomicAdd(&g_cnt[dst[e]], 1);
    }
}

__global__ __launch_bounds__(1024) void k_scan1() {
    __shared__ int s[1024];
    int t = threadIdx.x;
    int i = blockIdx.x * 1024 + t;
    int v = (i < NN) ? g_cnt[i] : 0;
    s[t] = v;
    __syncthreads();
    #pragma unroll
    for (int off = 1; off < 1024; off <<= 1) {
        int u = (t >= off) ? s[t - off] : 0;
        __syncthreads();
        s[t] += u;
        __syncthreads();
    }
    if (i < NN) g_offs[i] = s[t] - v;
    if (t == 1023) g_bsum[blockIdx.x] = s[1023];
}

__global__ void k_scanfix() {
    __shared__ int pre[2];
    int c0 = (blockIdx.x * 256) >> 10;
    if (threadIdx.x < 2) {
        int c = c0 + threadIdx.x;
        int sum = 0;
        for (int q = 0; q < c && q < NB; q++) sum += g_bsum[q];
        pre[threadIdx.x] = sum;
    }
    __syncthreads();
    int i = blockIdx.x * 256 + threadIdx.x;
    if (i >= NN) return;
    g_offs[i] += pre[(i >> 10) - c0];
    int c = g_cnt[i];
    float deg = (float)(c + 1);
    g_isqrt[i] = rsqrtf(deg);
    g_dinv[i]  = 1.0f / deg;
    g_cnt[i]   = 0;
    if (i == 0) g_offs[NN] = EE;
}

__global__ void k_scatter(const int* __restrict__ src, const int* __restrict__ dst) {
    int base = (blockIdx.x * blockDim.x + threadIdx.x) * 4;
    if (base + 4 <= EE) {
        int4 d = *(const int4*)(dst + base);
        int4 s = *(const int4*)(src + base);
        int p0 = g_offs[d.x] + atomicAdd(&g_cnt[d.x], 1);
        int p1 = g_offs[d.y] + atomicAdd(&g_cnt[d.y], 1);
        int p2 = g_offs[d.z] + atomicAdd(&g_cnt[d.z], 1);
        int p3 = g_offs[d.w] + atomicAdd(&g_cnt[d.w], 1);
        g_csrs[p0] = s.x; g_csre[p0] = base;
        g_csrs[p1] = s.y; g_csre[p1] = base + 1;
        g_csrs[p2] = s.z; g_csre[p2] = base + 2;
        g_csrs[p3] = s.w; g_csre[p3] = base + 3;
    } else {
        for (int e = base; e < EE; e++) {
            int d = dst[e];
            int pos = g_offs[d] + atomicAdd(&g_cnt[d], 1);
            g_csrs[pos] = src[e];
            g_csre[pos] = e;
        }
    }
}

// ---------------- weight fp16 conversion (side stream) -------------------------
__global__ void k_cvt(const float* __restrict__ W1, const float* __restrict__ Wmu,
                      const float* __restrict__ Wls) {
    int i = blockIdx.x * 256 + threadIdx.x;
    if (i < DD * DD) {
        g_w1h[i] = __float2half(W1[i]);
    } else if (i < 2 * DD * DD) {
        int j = i - DD * DD;
        int r = j >> 7, cc = j & 127;
        g_wabh[j] = __float2half(cc < 64 ? Wmu[r * 64 + cc] : Wls[r * 64 + (cc - 64)]);
    }
}

// ---------------- EmbeddingBag(sum, weighted) + L2 normalize -> fp16 ----------
__global__ void k_embed(const int* __restrict__ fidx, const int* __restrict__ foff,
                        const float* __restrict__ fw, const float* __restrict__ emb) {
    int w = (blockIdx.x * blockDim.x + threadIdx.x) >> 5;
    int lane = threadIdx.x & 31;
    if (w >= NN) return;
    int start = foff[w];
    int end = (w + 1 < NN) ? foff[w + 1] : TOT;
    float4 acc = make_float4(0.f, 0.f, 0.f, 0.f);
    int k = start;
    for (; k + 4 <= end; k += 4) {
        int i0 = fidx[k], i1 = fidx[k+1], i2 = fidx[k+2], i3 = fidx[k+3];
        float w0 = fw[k], w1 = fw[k+1], w2 = fw[k+2], w3 = fw[k+3];
        float4 v0 = ((const float4*)emb)[i0 * 32 + lane];
        float4 v1 = ((const float4*)emb)[i1 * 32 + lane];
        float4 v2 = ((const float4*)emb)[i2 * 32 + lane];
        float4 v3 = ((const float4*)emb)[i3 * 32 + lane];
        acc.x = fmaf(w0, v0.x, fmaf(w1, v1.x, fmaf(w2, v2.x, fmaf(w3, v3.x, acc.x))));
        acc.y = fmaf(w0, v0.y, fmaf(w1, v1.y, fmaf(w2, v2.y, fmaf(w3, v3.y, acc.y))));
        acc.z = fmaf(w0, v0.z, fmaf(w1, v1.z, fmaf(w2, v2.z, fmaf(w3, v3.z, acc.z))));
        acc.w = fmaf(w0, v0.w, fmaf(w1, v1.w, fmaf(w2, v2.w, fmaf(w3, v3.w, acc.w))));
    }
    for (; k < end; k++) {
        int idx = fidx[k];
        float wt = fw[k];
        float4 v = ((const float4*)emb)[idx * 32 + lane];
        acc.x = fmaf(wt, v.x, acc.x);
        acc.y = fmaf(wt, v.y, acc.y);
        acc.z = fmaf(wt, v.z, acc.z);
        acc.w = fmaf(wt, v.w, acc.w);
    }
    float ss = acc.x * acc.x + acc.y * acc.y + acc.z * acc.z + acc.w * acc.w;
    for (int o = 16; o > 0; o >>= 1) ss += __shfl_xor_sync(0xffffffffu, ss, o);
    float inv = 1.0f / fmaxf(sqrtf(ss), 1e-12f);
    __half2 h0 = __floats2half2_rn(acc.x * inv, acc.y * inv);
    __half2 h1 = __floats2half2_rn(acc.z * inv, acc.w * inv);
    uint2 u;
    u.x = *(unsigned*)&h0;
    u.y = *(unsigned*)&h1;
    ((uint2*)g_xh)[w * 32 + lane] = u;
}

// ---------------- generic HMMA GEMM: Y = A @ B (N x 128 @ 128 x 128), fp16 ----
__global__ __launch_bounds__(256) void k_gemmA(const __half* __restrict__ A,
                                               const __half* __restrict__ B,
                                               __half* __restrict__ Y) {
    __shared__ __align__(32) char smraw[49152];
    __half* sA = (__half*)smraw;                       // 64x128 = 16KB
    __half* sB = (__half*)(smraw + 16384);             // 128x128 = 32KB
    float (*sC)[16][68] = reinterpret_cast<float(*)[16][68]>(smraw);

    int t = threadIdx.x;
    int row0 = blockIdx.x * 64;

    #pragma unroll
    for (int q = 0; q < 4; q++) {
        int idx = t + q * 256;
        int r = idx >> 4, c4 = idx & 15;
        int gr = row0 + r;
        uint4 v = make_uint4(0u, 0u, 0u, 0u);
        if (gr < NN) v = ((const uint4*)A)[gr * 16 + c4];
        ((uint4*)sA)[idx] = v;
    }
    #pragma unroll
    for (int q = 0; q < 8; q++) {
        int idx = t + q * 256;
        ((uint4*)sB)[idx] = ((const uint4*)B)[idx];
    }
    __syncthreads();

    int w = t >> 5, lane = t & 31;
    int wr = w >> 1, wc = w & 1;

    wmma::fragment<wmma::accumulator, 16, 16, 16, float> c[4];
    #pragma unroll
    for (int j = 0; j < 4; j++) wmma::fill_fragment(c[j], 0.f);

    #pragma unroll
    for (int k0 = 0; k0 < 8; k0++) {
        wmma::fragment<wmma::matrix_a, 16, 16, 16, half, wmma::row_major> a;
        wmma::load_matrix_sync(a, sA + (wr * 16) * 128 + k0 * 16, 128);
        #pragma unroll
        for (int j = 0; j < 4; j++) {
            wmma::fragment<wmma::matrix_b, 16, 16, 16, half, wmma::row_major> b;
            wmma::load_matrix_sync(b, sB + (k0 * 16) * 128 + wc * 64 + j * 16, 128);
            wmma::mma_sync(c[j], a, b, c[j]);
        }
    }
    __syncthreads();

    #pragma unroll
    for (int j = 0; j < 4; j++)
        wmma::store_matrix_sync(&sC[w][0][j * 16], c[j], 68, wmma::mem_row_major);
    __syncwarp();
    int r = lane >> 1, ch = (lane & 1) * 32;
    int gr = row0 + wr * 16 + r;
    int col0 = wc * 64;
    if (gr < NN) {
        __align__(16) __half tmp[32];
        #pragma unroll
        for (int cc = 0; cc < 32; cc++)
            tmp[cc] = __float2half(sC[w][r][ch + cc]);
        uint4* dstp = (uint4*)(Y + (size_t)gr * 128 + col0 + ch);
        const uint4* srcp = (const uint4*)tmp;
        #pragma unroll
        for (int q = 0; q < 4; q++) dstp[q] = srcp[q];
    }
}

// ---------------- gather core: returns fp32 aggregated row slice --------------
__device__ __forceinline__ float4 agg_core(const uint2* __restrict__ in2, int n, int lane) {
    int lo = g_offs[n], hi = g_offs[n + 1];
    float4 acc = make_float4(0.f, 0.f, 0.f, 0.f);
    int p = lo;
    for (; p + 8 <= hi; p += 8) {
        int j[8];
        float wj[8];
        uint2 u[8];
        #pragma unroll
        for (int q = 0; q < 8; q++) j[q] = g_csrs[p + q];
        #pragma unroll
        for (int q = 0; q < 8; q++) wj[q] = g_isqrt[j[q]];
        #pragma unroll
        for (int q = 0; q < 8; q++) u[q] = in2[j[q] * 32 + lane];
        #pragma unroll
        for (int q = 0; q < 8; q++) {
            float2 f0 = __half22float2(*(__half2*)&u[q].x);
            float2 f1 = __half22float2(*(__half2*)&u[q].y);
            acc.x = fmaf(wj[q], f0.x, acc.x);
            acc.y = fmaf(wj[q], f0.y, acc.y);
            acc.z = fmaf(wj[q], f1.x, acc.z);
            acc.w = fmaf(wj[q], f1.y, acc.w);
        }
    }
    for (; p < hi; p++) {
        int jj = g_csrs[p];
        float wj = g_isqrt[jj];
        uint2 u = in2[jj * 32 + lane];
        float2 f0 = __half22float2(*(__half2*)&u.x);
        float2 f1 = __half22float2(*(__half2*)&u.y);
        acc.x = fmaf(wj, f0.x, acc.x);
        acc.y = fmaf(wj, f0.y, acc.y);
        acc.z = fmaf(wj, f1.x, acc.z);
        acc.w = fmaf(wj, f1.y, acc.w);
    }
    float si = g_isqrt[n], di = g_dinv[n];
    uint2 us = in2[n * 32 + lane];
    float2 s0 = __half22float2(*(__half2*)&us.x);
    float2 s1 = __half22float2(*(__half2*)&us.y);
    float4 o;
    o.x = acc.x * si + s0.x * di;
    o.y = acc.y * si + s0.y * di;
    o.z = acc.z * si + s1.x * di;
    o.w = acc.w * si + s1.y * di;
    return o;
}

// ---------------- agg + relu epilogue: h = relu(A~ y1 + b1) --------------------
__global__ void k_aggrelu(const __half* __restrict__ in, const float* __restrict__ b,
                          __half* __restrict__ out) {
    int w = (blockIdx.x * blockDim.x + threadIdx.x) >> 5;
    int lane = threadIdx.x & 31;
    if (w >= NN) return;
    float4 o = agg_core((const uint2*)in, w, lane);
    float4 bv = ((const float4*)b)[lane];
    o.x = fmaxf(o.x + bv.x, 0.f);
    o.y = fmaxf(o.y + bv.y, 0.f);
    o.z = fmaxf(o.z + bv.z, 0.f);
    o.w = fmaxf(o.w + bv.w, 0.f);
    __half2 h0 = __floats2half2_rn(o.x, o.y);
    __half2 h1 = __floats2half2_rn(o.z, o.w);
    uint2 u;
    u.x = *(unsigned*)&h0;
    u.y = *(unsigned*)&h1;
    ((uint2*)out)[w * 32 + lane] = u;
}

// ---------------- agg + z epilogue: z = (aggmu+bmu) + noise*exp(aggls+bls) ----
// lane<16 holds mu cols [4l,4l+4); lane>=16 holds ls cols [4l-64 .. ) of the
// ls half; ls lanes compute noise*exp(.), shfl down 16 to the mu lanes.
__global__ void k_aggz(const __half* __restrict__ in, const float* __restrict__ bmu,
                       const float* __restrict__ bls, const float* __restrict__ noise) {
    int w = (blockIdx.x * blockDim.x + threadIdx.x) >> 5;
    int lane = threadIdx.x & 31;
    if (w >= NN) return;
    float4 o = agg_core((const uint2*)in, w, lane);

    float4 e = make_float4(0.f, 0.f, 0.f, 0.f);
    if (lane >= 16) {
        int ob = lane * 4 - 64;
        float4 bv = ((const float4*)bls)[lane - 16];
        float4 nv = ((const float4*)(noise + (size_t)w * 64))[lane - 16];
        e.x = expf(o.x + bv.x) * nv.x;
        e.y = expf(o.y + bv.y) * nv.y;
        e.z = expf(o.z + bv.z) * nv.z;
        e.w = expf(o.w + bv.w) * nv.w;
        (void)ob;
    }
    e.x = __shfl_down_sync(0xffffffffu, e.x, 16);
    e.y = __shfl_down_sync(0xffffffffu, e.y, 16);
    e.z = __shfl_down_sync(0xffffffffu, e.z, 16);
    e.w = __shfl_down_sync(0xffffffffu, e.w, 16);
    if (lane < 16) {
        float4 bv = ((const float4*)bmu)[lane];
        float zx = o.x + bv.x + e.x;
        float zy = o.y + bv.y + e.y;
        float zz = o.z + bv.z + e.z;
        float zw = o.w + bv.w + e.w;
        __half2 h0 = __floats2half2_rn(zx, zy);
        __half2 h1 = __floats2half2_rn(zz, zw);
        uint2 u;
        u.x = *(unsigned*)&h0;
        u.y = *(unsigned*)&h1;
        ((uint2*)g_zh)[w * 16 + lane] = u;
    }
}

// ---------------- decoder (CSR-ordered): one warp per dst node -----------------
__global__ void k_dec(float* __restrict__ out) {
    int gid = blockIdx.x * blockDim.x + threadIdx.x;
    if (gid < NN) g_cnt[gid] = 0;            // re-zero for next replay
    int n = gid >> 5;
    if (n >= NN) return;
    int lane = threadIdx.x & 31;
    int g = lane >> 3, sl = lane & 7;
    unsigned gm = 0xffu << (g * 8);

    int lo = g_offs[n], hi = g_offs[n + 1];
    uint4 zd = ((const uint4*)g_zh)[n * 8 + sl];
    float2 d0 = __half22float2(*(__half2*)&zd.x);
    float2 d1 = __half22float2(*(__half2*)&zd.y);
    float2 d2 = __half22float2(*(__half2*)&zd.z);
    float2 d3 = __half22float2(*(__half2*)&zd.w);

    for (int p = lo + g; p < hi; p += 4) {
        int s = g_csrs[p];
        int eid = g_csre[p];
        uint4 za = ((const uint4*)g_zh)[s * 8 + sl];
        float2 a0 = __half22float2(*(__half2*)&za.x);
        float2 a1 = __half22float2(*(__half2*)&za.y);
        float2 a2 = __half22float2(*(__half2*)&za.z);
        float2 a3 = __half22float2(*(__half2*)&za.w);
        float v = a0.x * d0.x + a0.y * d0.y + a1.x * d1.x + a1.y * d1.y
                + a2.x * d2.x + a2.y * d2.y + a3.x * d3.x + a3.y * d3.y;
        v += __shfl_xor_sync(gm, v, 4);
        v += __shfl_xor_sync(gm, v, 2);
        v += __shfl_xor_sync(gm, v, 1);
        if (sl == 0) out[eid] = v;
    }
}

// ---------------- launch -------------------------------------------------------
extern "C" void kernel_launch(void* const* d_in, const int* in_sizes, int n_in,
                              void* d_out, int out_size) {
    const int*   fidx  = (const int*)d_in[0];
    const int*   foff  = (const int*)d_in[1];
    const float* fw    = (const float*)d_in[2];
    const int*   edge  = (const int*)d_in[3];
    const float* noise = (const float*)d_in[4];
    const float* emb   = (const float*)d_in[5];
    const float* W1    = (const float*)d_in[6];
    const float* b1    = (const float*)d_in[7];
    const float* Wmu   = (const float*)d_in[8];
    const float* bmu   = (const float*)d_in[9];
    const float* Wls   = (const float*)d_in[10];
    const float* bls   = (const float*)d_in[11];
    float* out = (float*)d_out;

    const int* src = edge;
    const int* dst = edge + EE;

    __half *pxh = nullptr, *py = nullptr, *phh = nullptr, *pw1 = nullptr, *pwab = nullptr;
    cudaGetSymbolAddress((void**)&pxh, g_xh);
    cudaGetSymbolAddress((void**)&py, g_y);
    cudaGetSymbolAddress((void**)&phh, g_hh);
    cudaGetSymbolAddress((void**)&pw1, g_w1h);
    cudaGetSymbolAddress((void**)&pwab, g_wabh);

    static cudaStream_t s2 = nullptr;
    static cudaEvent_t evF = nullptr, evJ = nullptr;
    static bool ok = false;
    if (!s2) {
        ok = (cudaStreamCreateWithFlags(&s2, cudaStreamNonBlocking) == cudaSuccess) &&
             (cudaEventCreateWithFlags(&evF, cudaEventDisableTiming) == cudaSuccess) &&
             (cudaEventCreateWithFlags(&evJ, cudaEventDisableTiming) == cudaSuccess);
    }

    cudaStream_t se = ok ? s2 : 0;
    if (ok) {
        cudaEventRecord(evF, 0);
        cudaStreamWaitEvent(s2, evF, 0);
    }
    // branch B (independent of CSR build): weights, embedding, y1 = x @ W1
    k_cvt<<<(2 * DD * DD + 255) / 256, 256, 0, se>>>(W1, Wmu, Wls);
    k_embed<<<(NN + 3) / 4, 128, 0, se>>>(fidx, foff, fw, emb);
    k_gemmA<<<(NN + 63) / 64, 256, 0, se>>>(pxh, pw1, py);
    if (ok) cudaEventRecord(evJ, s2);

    // branch A: CSR build (g_cnt zero at load; re-zeroed by k_dec tail each replay)
    k_hist<<<(EE / 8 + 255) / 256, 256>>>(dst);
    k_scan1<<<NB, 1024>>>();
    k_scanfix<<<(NN + 255) / 256, 256>>>();
    k_scatter<<<(EE / 4 + 255) / 256, 256>>>(src, dst);

    if (ok) cudaStreamWaitEvent(0, evJ, 0);

    k_aggrelu<<<(NN + 3) / 4, 128>>>(py, b1, phh);                // h = relu(A~y1 + b1)
    k_gemmA<<<(NN + 63) / 64, 256>>>(phh, pwab, py);              // y2 = h @ [Wmu|Wls]
    k_aggz<<<(NN + 3) / 4, 128>>>(py, bmu, bls, noise);           // z = agg epilogue
    k_dec<<<(NN * 32 + 255) / 256, 256>>>(out);
}

// round 10
// speedup vs baseline: 1.4004x; 1.0287x over previous
#include <cuda_runtime.h>
#include <cuda_fp16.h>
#include <mma.h>
#include <math.h>

using namespace nvcuda;

#define NN 50000
#define EE 1600000
#define VV 100000
#define DD 128
#define OO 64
#define TOT (NN*16)
#define NB 49   // ceil(NN/1024)

// ---------------- scratch (static device globals; no allocs allowed) ----------
__device__ int    g_cnt[NN];
__device__ int    g_offs[NN + 1];
__device__ int    g_csrs[EE];       // src sorted by dst
__device__ int    g_csre[EE];       // eid sorted by dst
__device__ volatile int g_blksum[NB];
__device__ volatile int g_blkflag[NB];
__device__ float  g_isqrt[NN];
__device__ __half g_xh[NN * DD];    // embedding output (fp16)
__device__ __half g_y[NN * DD];     // pre-scaled GEMM output (y' = isqrt*y)
__device__ __half g_hh[NN * DD];    // relu layer-1 output (fp16)
__device__ __half g_zh[NN * OO];    // z (fp16)
__device__ __half g_w1h[DD * DD];   // W1 fp16
__device__ __half g_wabh[DD * DD];  // [Wmu|Wls] fp16

// ---------------- CSR build ---------------------------------------------------
__global__ void k_hist(const int* __restrict__ dst) {
    int base = (blockIdx.x * blockDim.x + threadIdx.x) * 8;
    if (base + 8 <= EE) {
        int4 d0 = *(const int4*)(dst + base);
        int4 d1 = *(const int4*)(dst + base + 4);
        atomicAdd(&g_cnt[d0.x], 1);
        atomicAdd(&g_cnt[d0.y], 1);
        atomicAdd(&g_cnt[d0.z], 1);
        atomicAdd(&g_cnt[d0.w], 1);
        atomicAdd(&g_cnt[d1.x], 1);
        atomicAdd(&g_cnt[d1.y], 1);
        atomicAdd(&g_cnt[d1.z], 1);
        atomicAdd(&g_cnt[d1.w], 1);
    } else {
        for (int e = base; e < EE; e++) atomicAdd(&g_cnt[dst[e]], 1);
    }
}

// single-kernel chained scan: 49 blocks, all resident; flags pre-zeroed
// (static init for first run; k_dec tail re-zeroes for each replay)
__global__ __launch_bounds__(1024) void k_scan() {
    __shared__ int s[1024];
    __shared__ int spre;
    int t = threadIdx.x, b = blockIdx.x;
    int i = b * 1024 + t;
    int v = (i < NN) ? g_cnt[i] : 0;
    s[t] = v;
    __syncthreads();
    #pragma unroll
    for (int off = 1; off < 1024; off <<= 1) {
        int u = (t >= off) ? s[t - off] : 0;
        __syncthreads();
        s[t] += u;
        __syncthreads();
    }
    if (t == 1023) {
        g_blksum[b] = s[1023];
        __threadfence();
        g_blkflag[b] = 1;
        int pre = 0;
        for (int q = 0; q < b; q++) {
            while (g_blkflag[q] == 0) { }
            pre += g_blksum[q];
        }
        spre = pre;
    }
    __syncthreads();
    if (i < NN) {
        g_offs[i] = spre + s[t] - v;       // exclusive prefix
        float deg = (float)(v + 1);
        g_isqrt[i] = rsqrtf(deg);
        g_cnt[i]   = 0;                    // cursor for scatter
        if (i == 0) g_offs[NN] = EE;
    }
}

__global__ void k_scatter(const int* __restrict__ src, const int* __restrict__ dst) {
    int base = (blockIdx.x * blockDim.x + threadIdx.x) * 4;
    if (base + 4 <= EE) {
        int4 d = *(const int4*)(dst + base);
        int4 s = *(const int4*)(src + base);
        int p0 = g_offs[d.x] + atomicAdd(&g_cnt[d.x], 1);
        int p1 = g_offs[d.y] + atomicAdd(&g_cnt[d.y], 1);
        int p2 = g_offs[d.z] + atomicAdd(&g_cnt[d.z], 1);
        int p3 = g_offs[d.w] + atomicAdd(&g_cnt[d.w], 1);
        g_csrs[p0] = s.x; g_csre[p0] = base;
        g_csrs[p1] = s.y; g_csre[p1] = base + 1;
        g_csrs[p2] = s.z; g_csre[p2] = base + 2;
        g_csrs[p3] = s.w; g_csre[p3] = base + 3;
    } else {
        for (int e = base; e < EE; e++) {
            int d = dst[e];
            int pos = g_offs[d] + atomicAdd(&g_cnt[d], 1);
            g_csrs[pos] = src[e];
            g_csre[pos] = e;
        }
    }
}

// ---------------- weight fp16 conversion (side stream) -------------------------
__global__ void k_cvt(const float* __restrict__ W1, const float* __restrict__ Wmu,
                      const float* __restrict__ Wls) {
    int i = blockIdx.x * 256 + threadIdx.x;
    if (i < DD * DD) {
        g_w1h[i] = __float2half(W1[i]);
    } else if (i < 2 * DD * DD) {
        int j = i - DD * DD;
        int r = j >> 7, cc = j & 127;
        g_wabh[j] = __float2half(cc < 64 ? Wmu[r * 64 + cc] : Wls[r * 64 + (cc - 64)]);
    }
}

// ---------------- EmbeddingBag(sum, weighted) + L2 normalize -> fp16 ----------
__global__ void k_embed(const int* __restrict__ fidx, const int* __restrict__ foff,
                        const float* __restrict__ fw, const float* __restrict__ emb) {
    int w = (blockIdx.x * blockDim.x + threadIdx.x) >> 5;
    int lane = threadIdx.x & 31;
    if (w >= NN) return;
    int start = foff[w];
    int end = (w + 1 < NN) ? foff[w + 1] : TOT;
    float4 acc = make_float4(0.f, 0.f, 0.f, 0.f);
    int k = start;
    for (; k + 4 <= end; k += 4) {
        int i0 = fidx[k], i1 = fidx[k+1], i2 = fidx[k+2], i3 = fidx[k+3];
        float w0 = fw[k], w1 = fw[k+1], w2 = fw[k+2], w3 = fw[k+3];
        float4 v0 = ((const float4*)emb)[i0 * 32 + lane];
        float4 v1 = ((const float4*)emb)[i1 * 32 + lane];
        float4 v2 = ((const float4*)emb)[i2 * 32 + lane];
        float4 v3 = ((const float4*)emb)[i3 * 32 + lane];
        acc.x = fmaf(w0, v0.x, fmaf(w1, v1.x, fmaf(w2, v2.x, fmaf(w3, v3.x, acc.x))));
        acc.y = fmaf(w0, v0.y, fmaf(w1, v1.y, fmaf(w2, v2.y, fmaf(w3, v3.y, acc.y))));
        acc.z = fmaf(w0, v0.z, fmaf(w1, v1.z, fmaf(w2, v2.z, fmaf(w3, v3.z, acc.z))));
        acc.w = fmaf(w0, v0.w, fmaf(w1, v1.w, fmaf(w2, v2.w, fmaf(w3, v3.w, acc.w))));
    }
    for (; k < end; k++) {
        int idx = fidx[k];
        float wt = fw[k];
        float4 v = ((const float4*)emb)[idx * 32 + lane];
        acc.x = fmaf(wt, v.x, acc.x);
        acc.y = fmaf(wt, v.y, acc.y);
        acc.z = fmaf(wt, v.z, acc.z);
        acc.w = fmaf(wt, v.w, acc.w);
    }
    float ss = acc.x * acc.x + acc.y * acc.y + acc.z * acc.z + acc.w * acc.w;
    for (int o = 16; o > 0; o >>= 1) ss += __shfl_xor_sync(0xffffffffu, ss, o);
    float inv = 1.0f / fmaxf(sqrtf(ss), 1e-12f);
    __half2 h0 = __floats2half2_rn(acc.x * inv, acc.y * inv);
    __half2 h1 = __floats2half2_rn(acc.z * inv, acc.w * inv);
    uint2 u;
    u.x = *(unsigned*)&h0;
    u.y = *(unsigned*)&h1;
    ((uint2*)g_xh)[w * 32 + lane] = u;
}

// ---------------- HMMA GEMM with isqrt-prescaled epilogue: Y = diag(isqrt)(A@B)
__global__ __launch_bounds__(256) void k_gemmA(const __half* __restrict__ A,
                                               const __half* __restrict__ B,
                                               __half* __restrict__ Y) {
    __shared__ __align__(32) char smraw[49152];
    __half* sA = (__half*)smraw;                       // 64x128 = 16KB
    __half* sB = (__half*)(smraw + 16384);             // 128x128 = 32KB
    float (*sC)[16][68] = reinterpret_cast<float(*)[16][68]>(smraw);

    int t = threadIdx.x;
    int row0 = blockIdx.x * 64;

    #pragma unroll
    for (int q = 0; q < 4; q++) {
        int idx = t + q * 256;
        int r = idx >> 4, c4 = idx & 15;
        int gr = row0 + r;
        uint4 v = make_uint4(0u, 0u, 0u, 0u);
        if (gr < NN) v = ((const uint4*)A)[gr * 16 + c4];
        ((uint4*)sA)[idx] = v;
    }
    #pragma unroll
    for (int q = 0; q < 8; q++) {
        int idx = t + q * 256;
        ((uint4*)sB)[idx] = ((const uint4*)B)[idx];
    }
    __syncthreads();

    int w = t >> 5, lane = t & 31;
    int wr = w >> 1, wc = w & 1;

    wmma::fragment<wmma::accumulator, 16, 16, 16, float> c[4];
    #pragma unroll
    for (int j = 0; j < 4; j++) wmma::fill_fragment(c[j], 0.f);

    #pragma unroll
    for (int k0 = 0; k0 < 8; k0++) {
        wmma::fragment<wmma::matrix_a, 16, 16, 16, half, wmma::row_major> a;
        wmma::load_matrix_sync(a, sA + (wr * 16) * 128 + k0 * 16, 128);
        #pragma unroll
        for (int j = 0; j < 4; j++) {
            wmma::fragment<wmma::matrix_b, 16, 16, 16, half, wmma::row_major> b;
            wmma::load_matrix_sync(b, sB + (k0 * 16) * 128 + wc * 64 + j * 16, 128);
            wmma::mma_sync(c[j], a, b, c[j]);
        }
    }
    __syncthreads();

    #pragma unroll
    for (int j = 0; j < 4; j++)
        wmma::store_matrix_sync(&sC[w][0][j * 16], c[j], 68, wmma::mem_row_major);
    __syncwarp();
    int r = lane >> 1, ch = (lane & 1) * 32;
    int gr = row0 + wr * 16 + r;
    int col0 = wc * 64;
    if (gr < NN) {
        float sc = g_isqrt[gr];
        __align__(16) __half tmp[32];
        #pragma unroll
        for (int cc = 0; cc < 32; cc++)
            tmp[cc] = __float2half(sC[w][r][ch + cc] * sc);
        uint4* dstp = (uint4*)(Y + (size_t)gr * 128 + col0 + ch);
        const uint4* srcp = (const uint4*)tmp;
        #pragma unroll
        for (int q = 0; q < 4; q++) dstp[q] = srcp[q];
    }
}

// ---------------- gather core: out = isqrt_n * (sum_j y'_j + y'_n) -------------
__device__ __forceinline__ float4 agg_core(const uint2* __restrict__ in2, int n, int lane) {
    int lo = g_offs[n], hi = g_offs[n + 1];
    float4 acc = make_float4(0.f, 0.f, 0.f, 0.f);
    int p = lo;
    for (; p + 8 <= hi; p += 8) {
        int j[8];
        uint2 u[8];
        #pragma unroll
        for (int q = 0; q < 8; q++) j[q] = g_csrs[p + q];
        #pragma unroll
        for (int q = 0; q < 8; q++) u[q] = in2[j[q] * 32 + lane];
        #pragma unroll
        for (int q = 0; q < 8; q++) {
            float2 f0 = __half22float2(*(__half2*)&u[q].x);
            float2 f1 = __half22float2(*(__half2*)&u[q].y);
            acc.x += f0.x;
            acc.y += f0.y;
            acc.z += f1.x;
            acc.w += f1.y;
        }
    }
    for (; p < hi; p++) {
        int jj = g_csrs[p];
        uint2 u = in2[jj * 32 + lane];
        float2 f0 = __half22float2(*(__half2*)&u.x);
        float2 f1 = __half22float2(*(__half2*)&u.y);
        acc.x += f0.x;
        acc.y += f0.y;
        acc.z += f1.x;
        acc.w += f1.y;
    }
    uint2 us = in2[n * 32 + lane];
    float2 s0 = __half22float2(*(__half2*)&us.x);
    float2 s1 = __half22float2(*(__half2*)&us.y);
    float si = g_isqrt[n];
    float4 o;
    o.x = (acc.x + s0.x) * si;
    o.y = (acc.y + s0.y) * si;
    o.z = (acc.z + s1.x) * si;
    o.w = (acc.w + s1.y) * si;
    return o;
}

// ---------------- agg + relu epilogue: h = relu(agg(y1') + b1) -----------------
__global__ void k_aggrelu(const __half* __restrict__ in, const float* __restrict__ b,
                          __half* __restrict__ out) {
    int w = (blockIdx.x * blockDim.x + threadIdx.x) >> 5;
    int lane = threadIdx.x & 31;
    if (w >= NN) return;
    float4 o = agg_core((const uint2*)in, w, lane);
    float4 bv = ((const float4*)b)[lane];
    o.x = fmaxf(o.x + bv.x, 0.f);
    o.y = fmaxf(o.y + bv.y, 0.f);
    o.z = fmaxf(o.z + bv.z, 0.f);
    o.w = fmaxf(o.w + bv.w, 0.f);
    __half2 h0 = __floats2half2_rn(o.x, o.y);
    __half2 h1 = __floats2half2_rn(o.z, o.w);
    uint2 u;
    u.x = *(unsigned*)&h0;
    u.y = *(unsigned*)&h1;
    ((uint2*)out)[w * 32 + lane] = u;
}

// ---------------- agg + z epilogue: z = (aggmu+bmu) + noise*exp(aggls+bls) ----
__global__ void k_aggz(const __half* __restrict__ in, const float* __restrict__ bmu,
                       const float* __restrict__ bls, const float* __restrict__ noise) {
    int w = (blockIdx.x * blockDim.x + threadIdx.x) >> 5;
    int lane = threadIdx.x & 31;
    if (w >= NN) return;
    float4 o = agg_core((const uint2*)in, w, lane);

    float4 e = make_float4(0.f, 0.f, 0.f, 0.f);
    if (lane >= 16) {
        float4 bv = ((const float4*)bls)[lane - 16];
        float4 nv = ((const float4*)(noise + (size_t)w * 64))[lane - 16];
        e.x = expf(o.x + bv.x) * nv.x;
        e.y = expf(o.y + bv.y) * nv.y;
        e.z = expf(o.z + bv.z) * nv.z;
        e.w = expf(o.w + bv.w) * nv.w;
    }
    e.x = __shfl_down_sync(0xffffffffu, e.x, 16);
    e.y = __shfl_down_sync(0xffffffffu, e.y, 16);
    e.z = __shfl_down_sync(0xffffffffu, e.z, 16);
    e.w = __shfl_down_sync(0xffffffffu, e.w, 16);
    if (lane < 16) {
        float4 bv = ((const float4*)bmu)[lane];
        float zx = o.x + bv.x + e.x;
        float zy = o.y + bv.y + e.y;
        float zz = o.z + bv.z + e.z;
        float zw = o.w + bv.w + e.w;
        __half2 h0 = __floats2half2_rn(zx, zy);
        __half2 h1 = __floats2half2_rn(zz, zw);
        uint2 u;
        u.x = *(unsigned*)&h0;
        u.y = *(unsigned*)&h1;
        ((uint2*)g_zh)[w * 16 + lane] = u;
    }
}

// ---------------- decoder (CSR-ordered) + scratch re-zero ----------------------
__global__ void k_dec(float* __restrict__ out) {
    int gid = blockIdx.x * blockDim.x + threadIdx.x;
    if (gid < NN) g_cnt[gid] = 0;            // re-zero for next replay
    if (gid < NB) g_blkflag[gid] = 0;        // re-arm the chained scan
    int n = gid >> 5;
    if (n >= NN) return;
    int lane = threadIdx.x & 31;
    int g = lane >> 3, sl = lane & 7;
    unsigned gm = 0xffu << (g * 8);

    int lo = g_offs[n], hi = g_offs[n + 1];
    uint4 zd = ((const uint4*)g_zh)[n * 8 + sl];
    float2 d0 = __half22float2(*(__half2*)&zd.x);
    float2 d1 = __half22float2(*(__half2*)&zd.y);
    float2 d2 = __half22float2(*(__half2*)&zd.z);
    float2 d3 = __half22float2(*(__half2*)&zd.w);

    for (int p = lo + g; p < hi; p += 4) {
        int s = g_csrs[p];
        int eid = g_csre[p];
        uint4 za = ((const uint4*)g_zh)[s * 8 + sl];
        float2 a0 = __half22float2(*(__half2*)&za.x);
        float2 a1 = __half22float2(*(__half2*)&za.y);
        float2 a2 = __half22float2(*(__half2*)&za.z);
        float2 a3 = __half22float2(*(__half2*)&za.w);
        float v = a0.x * d0.x + a0.y * d0.y + a1.x * d1.x + a1.y * d1.y
                + a2.x * d2.x + a2.y * d2.y + a3.x * d3.x + a3.y * d3.y;
        v += __shfl_xor_sync(gm, v, 4);
        v += __shfl_xor_sync(gm, v, 2);
        v += __shfl_xor_sync(gm, v, 1);
        if (sl == 0) out[eid] = v;
    }
}

// ---------------- launch -------------------------------------------------------
extern "C" void kernel_launch(void* const* d_in, const int* in_sizes, int n_in,
                              void* d_out, int out_size) {
    const int*   fidx  = (const int*)d_in[0];
    const int*   foff  = (const int*)d_in[1];
    const float* fw    = (const float*)d_in[2];
    const int*   edge  = (const int*)d_in[3];
    const float* noise = (const float*)d_in[4];
    const float* emb   = (const float*)d_in[5];
    const float* W1    = (const float*)d_in[6];
    const float* b1    = (const float*)d_in[7];
    const float* Wmu   = (const float*)d_in[8];
    const float* bmu   = (const float*)d_in[9];
    const float* Wls   = (const float*)d_in[10];
    const float* bls   = (const float*)d_in[11];
    float* out = (float*)d_out;

    const int* src = edge;
    const int* dst = edge + EE;

    __half *pxh = nullptr, *py = nullptr, *phh = nullptr, *pw1 = nullptr, *pwab = nullptr;
    cudaGetSymbolAddress((void**)&pxh, g_xh);
    cudaGetSymbolAddress((void**)&py, g_y);
    cudaGetSymbolAddress((void**)&phh, g_hh);
    cudaGetSymbolAddress((void**)&pw1, g_w1h);
    cudaGetSymbolAddress((void**)&pwab, g_wabh);

    static cudaStream_t s2 = nullptr;
    static cudaEvent_t evF = nullptr, evS = nullptr, evJ = nullptr;
    static bool ok = false;
    if (!s2) {
        ok = (cudaStreamCreateWithFlags(&s2, cudaStreamNonBlocking) == cudaSuccess) &&
             (cudaEventCreateWithFlags(&evF, cudaEventDisableTiming) == cudaSuccess) &&
             (cudaEventCreateWithFlags(&evS, cudaEventDisableTiming) == cudaSuccess) &&
             (cudaEventCreateWithFlags(&evJ, cudaEventDisableTiming) == cudaSuccess);
    }

    if (!ok) {
        // fallback: fully serial on default stream
        k_hist<<<(EE / 8 + 255) / 256, 256>>>(dst);
        k_scan<<<NB, 1024>>>();
        k_scatter<<<(EE / 4 + 255) / 256, 256>>>(src, dst);
        k_cvt<<<(2 * DD * DD + 255) / 256, 256>>>(W1, Wmu, Wls);
        k_embed<<<(NN + 3) / 4, 128>>>(fidx, foff, fw, emb);
        k_gemmA<<<(NN + 63) / 64, 256>>>(pxh, pw1, py);
        k_aggrelu<<<(NN + 3) / 4, 128>>>(py, b1, phh);
        k_gemmA<<<(NN + 63) / 64, 256>>>(phh, pwab, py);
        k_aggz<<<(NN + 3) / 4, 128>>>(py, bmu, bls, noise);
        k_dec<<<(NN * 32 + 255) / 256, 256>>>(out);
        return;
    }

    // fork
    cudaEventRecord(evF, 0);
    cudaStreamWaitEvent(s2, evF, 0);

    // branch B (s2): weights + embedding (no CSR dependence)
    k_cvt<<<(2 * DD * DD + 255) / 256, 256, 0, s2>>>(W1, Wmu, Wls);
    k_embed<<<(NN + 3) / 4, 128, 0, s2>>>(fidx, foff, fw, emb);

    // branch A (default): hist + scan (produces isqrt), then scatter
    k_hist<<<(EE / 8 + 255) / 256, 256>>>(dst);
    k_scan<<<NB, 1024>>>();
    cudaEventRecord(evS, 0);                 // isqrt ready
    k_scatter<<<(EE / 4 + 255) / 256, 256>>>(src, dst);

    // branch B continues: gemm1' needs isqrt (prescaled epilogue)
    cudaStreamWaitEvent(s2, evS, 0);
    k_gemmA<<<(NN + 63) / 64, 256, 0, s2>>>(pxh, pw1, py);   // y1' = isqrt*(x@W1)
    cudaEventRecord(evJ, s2);

    // join, then the serial back half
    cudaStreamWaitEvent(0, evJ, 0);
    k_aggrelu<<<(NN + 3) / 4, 128>>>(py, b1, phh);           // h = relu(agg(y1')+b1)
    k_gemmA<<<(NN + 63) / 64, 256>>>(phh, pwab, py);         // y2' = isqrt*(h@[Wmu|Wls])
    k_aggz<<<(NN + 3) / 4, 128>>>(py, bmu, bls, noise);      // z
    k_dec<<<(NN * 32 + 255) / 256, 256>>>(out);
}

// round 11
// speedup vs baseline: 1.4800x; 1.0569x over previous
#include <cuda_runtime.h>
#include <cuda_fp16.h>
#include <mma.h>
#include <math.h>

using namespace nvcuda;

#define NN 50000
#define EE 1600000
#define VV 100000
#define DD 128
#define OO 64
#define TOT (NN*16)
#define NB 49   // ceil(NN/1024)

// ---------------- scratch (static device globals; no allocs allowed) ----------
__device__ int    g_cnt[NN];
__device__ int    g_offs[NN + 1];
__device__ int    g_csrs[EE];       // src sorted by dst
__device__ int    g_csre[EE];       // eid sorted by dst
__device__ volatile int g_blksum[NB];
__device__ volatile int g_blkflag[NB];
__device__ float  g_isqrt[NN];
__device__ __half g_xh[NN * DD];    // embedding output (fp16)
__device__ __half g_y[NN * DD];     // pre-scaled GEMM output (y' = isqrt*y)
__device__ __half g_hh[NN * DD];    // relu layer-1 output (fp16)
__device__ __half g_zh[NN * OO];    // z (fp16)
__device__ __half g_w1h[DD * DD];   // W1 fp16
__device__ __half g_wabh[DD * DD];  // [Wmu|Wls] fp16

// ---------------- CSR build ---------------------------------------------------
__global__ void k_hist(const int* __restrict__ dst) {
    int base = (blockIdx.x * blockDim.x + threadIdx.x) * 8;
    if (base + 8 <= EE) {
        int4 d0 = *(const int4*)(dst + base);
        int4 d1 = *(const int4*)(dst + base + 4);
        atomicAdd(&g_cnt[d0.x], 1);
        atomicAdd(&g_cnt[d0.y], 1);
        atomicAdd(&g_cnt[d0.z], 1);
        atomicAdd(&g_cnt[d0.w], 1);
        atomicAdd(&g_cnt[d1.x], 1);
        atomicAdd(&g_cnt[d1.y], 1);
        atomicAdd(&g_cnt[d1.z], 1);
        atomicAdd(&g_cnt[d1.w], 1);
    } else {
        for (int e = base; e < EE; e++) atomicAdd(&g_cnt[dst[e]], 1);
    }
}

// single-kernel chained scan with PARALLEL lookback (49 resident blocks)
__global__ __launch_bounds__(1024) void k_scan() {
    __shared__ int s[1024];
    __shared__ int pre_s[64];
    int t = threadIdx.x, b = blockIdx.x;
    int i = b * 1024 + t;
    int v = (i < NN) ? g_cnt[i] : 0;
    s[t] = v;
    if (t < 64) pre_s[t] = 0;
    __syncthreads();
    #pragma unroll
    for (int off = 1; off < 1024; off <<= 1) {
        int u = (t >= off) ? s[t - off] : 0;
        __syncthreads();
        s[t] += u;
        __syncthreads();
    }
    if (t == 1023) {
        g_blksum[b] = s[1023];
        __threadfence();
        g_blkflag[b] = 1;
    }
    // parallel lookback: each thread polls one predecessor
    if (t < b) {
        while (g_blkflag[t] == 0) { }
        pre_s[t] = g_blksum[t];
    }
    __syncthreads();
    if (t < 32) {
        int a = pre_s[t] + pre_s[t + 32];
        #pragma unroll
        for (int o = 16; o > 0; o >>= 1) a += __shfl_down_sync(0xffffffffu, a, o);
        if (t == 0) pre_s[0] = a;
    }
    __syncthreads();
    int spre = pre_s[0];
    if (i < NN) {
        g_offs[i] = spre + s[t] - v;       // exclusive prefix
        float deg = (float)(v + 1);
        g_isqrt[i] = rsqrtf(deg);
        g_cnt[i]   = 0;                    // cursor for scatter
        if (i == 0) g_offs[NN] = EE;
    }
}

__global__ void k_scatter(const int* __restrict__ src, const int* __restrict__ dst) {
    int base = (blockIdx.x * blockDim.x + threadIdx.x) * 4;
    if (base + 4 <= EE) {
        int4 d = *(const int4*)(dst + base);
        int4 s = *(const int4*)(src + base);
        int p0 = g_offs[d.x] + atomicAdd(&g_cnt[d.x], 1);
        int p1 = g_offs[d.y] + atomicAdd(&g_cnt[d.y], 1);
        int p2 = g_offs[d.z] + atomicAdd(&g_cnt[d.z], 1);
        int p3 = g_offs[d.w] + atomicAdd(&g_cnt[d.w], 1);
        g_csrs[p0] = s.x; g_csre[p0] = base;
        g_csrs[p1] = s.y; g_csre[p1] = base + 1;
        g_csrs[p2] = s.z; g_csre[p2] = base + 2;
        g_csrs[p3] = s.w; g_csre[p3] = base + 3;
    } else {
        for (int e = base; e < EE; e++) {
            int d = dst[e];
            int pos = g_offs[d] + atomicAdd(&g_cnt[d], 1);
            g_csrs[pos] = src[e];
            g_csre[pos] = e;
        }
    }
}

// ---------------- weight fp16 conversion (side stream) -------------------------
__global__ void k_cvt(const float* __restrict__ W1, const float* __restrict__ Wmu,
                      const float* __restrict__ Wls) {
    int i = blockIdx.x * 256 + threadIdx.x;
    if (i < DD * DD) {
        g_w1h[i] = __float2half(W1[i]);
    } else if (i < 2 * DD * DD) {
        int j = i - DD * DD;
        int r = j >> 7, cc = j & 127;
        g_wabh[j] = __float2half(cc < 64 ? Wmu[r * 64 + cc] : Wls[r * 64 + (cc - 64)]);
    }
}

// ---------------- EmbeddingBag(sum, weighted) + L2 normalize -> fp16 ----------
__global__ void k_embed(const int* __restrict__ fidx, const int* __restrict__ foff,
                        const float* __restrict__ fw, const float* __restrict__ emb) {
    int w = (blockIdx.x * blockDim.x + threadIdx.x) >> 5;
    int lane = threadIdx.x & 31;
    if (w >= NN) return;
    int start = foff[w];
    int end = (w + 1 < NN) ? foff[w + 1] : TOT;
    float4 acc = make_float4(0.f, 0.f, 0.f, 0.f);
    if (end - start == 16) {
        // fast path: two fully-unrolled 8-gather batches (8 loads in flight)
        #pragma unroll
        for (int kb = 0; kb < 2; kb++) {
            int k0 = start + kb * 8;
            int idx[8];
            float wt[8];
            float4 vv[8];
            #pragma unroll
            for (int q = 0; q < 8; q++) idx[q] = fidx[k0 + q];
            #pragma unroll
            for (int q = 0; q < 8; q++) wt[q] = fw[k0 + q];
            #pragma unroll
            for (int q = 0; q < 8; q++) vv[q] = ((const float4*)emb)[idx[q] * 32 + lane];
            #pragma unroll
            for (int q = 0; q < 8; q++) {
                acc.x = fmaf(wt[q], vv[q].x, acc.x);
                acc.y = fmaf(wt[q], vv[q].y, acc.y);
                acc.z = fmaf(wt[q], vv[q].z, acc.z);
                acc.w = fmaf(wt[q], vv[q].w, acc.w);
            }
        }
    } else {
        int k = start;
        for (; k + 4 <= end; k += 4) {
            int i0 = fidx[k], i1 = fidx[k+1], i2 = fidx[k+2], i3 = fidx[k+3];
            float w0 = fw[k], w1 = fw[k+1], w2 = fw[k+2], w3 = fw[k+3];
            float4 v0 = ((const float4*)emb)[i0 * 32 + lane];
            float4 v1 = ((const float4*)emb)[i1 * 32 + lane];
            float4 v2 = ((const float4*)emb)[i2 * 32 + lane];
            float4 v3 = ((const float4*)emb)[i3 * 32 + lane];
            acc.x = fmaf(w0, v0.x, fmaf(w1, v1.x, fmaf(w2, v2.x, fmaf(w3, v3.x, acc.x))));
            acc.y = fmaf(w0, v0.y, fmaf(w1, v1.y, fmaf(w2, v2.y, fmaf(w3, v3.y, acc.y))));
            acc.z = fmaf(w0, v0.z, fmaf(w1, v1.z, fmaf(w2, v2.z, fmaf(w3, v3.z, acc.z))));
            acc.w = fmaf(w0, v0.w, fmaf(w1, v1.w, fmaf(w2, v2.w, fmaf(w3, v3.w, acc.w))));
        }
        for (; k < end; k++) {
            int idx = fidx[k];
            float wt = fw[k];
            float4 v = ((const float4*)emb)[idx * 32 + lane];
            acc.x = fmaf(wt, v.x, acc.x);
            acc.y = fmaf(wt, v.y, acc.y);
            acc.z = fmaf(wt, v.z, acc.z);
            acc.w = fmaf(wt, v.w, acc.w);
        }
    }
    float ss = acc.x * acc.x + acc.y * acc.y + acc.z * acc.z + acc.w * acc.w;
    for (int o = 16; o > 0; o >>= 1) ss += __shfl_xor_sync(0xffffffffu, ss, o);
    float inv = 1.0f / fmaxf(sqrtf(ss), 1e-12f);
    __half2 h0 = __floats2half2_rn(acc.x * inv, acc.y * inv);
    __half2 h1 = __floats2half2_rn(acc.z * inv, acc.w * inv);
    uint2 u;
    u.x = *(unsigned*)&h0;
    u.y = *(unsigned*)&h1;
    ((uint2*)g_xh)[w * 32 + lane] = u;
}

// ---------------- HMMA GEMM with isqrt-prescaled epilogue: Y = diag(isqrt)(A@B)
__global__ __launch_bounds__(256) void k_gemmA(const __half* __restrict__ A,
                                               const __half* __restrict__ B,
                                               __half* __restrict__ Y) {
    __shared__ __align__(32) char smraw[49152];
    __half* sA = (__half*)smraw;                       // 64x128 = 16KB
    __half* sB = (__half*)(smraw + 16384);             // 128x128 = 32KB
    float (*sC)[16][68] = reinterpret_cast<float(*)[16][68]>(smraw);

    int t = threadIdx.x;
    int row0 = blockIdx.x * 64;

    #pragma unroll
    for (int q = 0; q < 4; q++) {
        int idx = t + q * 256;
        int r = idx >> 4, c4 = idx & 15;
        int gr = row0 + r;
        uint4 v = make_uint4(0u, 0u, 0u, 0u);
        if (gr < NN) v = ((const uint4*)A)[gr * 16 + c4];
        ((uint4*)sA)[idx] = v;
    }
    #pragma unroll
    for (int q = 0; q < 8; q++) {
        int idx = t + q * 256;
        ((uint4*)sB)[idx] = ((const uint4*)B)[idx];
    }
    __syncthreads();

    int w = t >> 5, lane = t & 31;
    int wr = w >> 1, wc = w & 1;

    wmma::fragment<wmma::accumulator, 16, 16, 16, float> c[4];
    #pragma unroll
    for (int j = 0; j < 4; j++) wmma::fill_fragment(c[j], 0.f);

    #pragma unroll
    for (int k0 = 0; k0 < 8; k0++) {
        wmma::fragment<wmma::matrix_a, 16, 16, 16, half, wmma::row_major> a;
        wmma::load_matrix_sync(a, sA + (wr * 16) * 128 + k0 * 16, 128);
        #pragma unroll
        for (int j = 0; j < 4; j++) {
            wmma::fragment<wmma::matrix_b, 16, 16, 16, half, wmma::row_major> b;
            wmma::load_matrix_sync(b, sB + (k0 * 16) * 128 + wc * 64 + j * 16, 128);
            wmma::mma_sync(c[j], a, b, c[j]);
        }
    }
    __syncthreads();

    #pragma unroll
    for (int j = 0; j < 4; j++)
        wmma::store_matrix_sync(&sC[w][0][j * 16], c[j], 68, wmma::mem_row_major);
    __syncwarp();
    int r = lane >> 1, ch = (lane & 1) * 32;
    int gr = row0 + wr * 16 + r;
    int col0 = wc * 64;
    if (gr < NN) {
        float sc = g_isqrt[gr];
        __align__(16) __half tmp[32];
        #pragma unroll
        for (int cc = 0; cc < 32; cc++)
            tmp[cc] = __float2half(sC[w][r][ch + cc] * sc);
        uint4* dstp = (uint4*)(Y + (size_t)gr * 128 + col0 + ch);
        const uint4* srcp = (const uint4*)tmp;
        #pragma unroll
        for (int q = 0; q < 4; q++) dstp[q] = srcp[q];
    }
}

// ---------------- gather core: out = isqrt_n * (sum_j y'_j + y'_n) -------------
__device__ __forceinline__ float4 agg_core(const uint2* __restrict__ in2, int n, int lane) {
    int lo = g_offs[n], hi = g_offs[n + 1];
    float4 acc = make_float4(0.f, 0.f, 0.f, 0.f);
    int p = lo;
    for (; p + 8 <= hi; p += 8) {
        int j[8];
        uint2 u[8];
        #pragma unroll
        for (int q = 0; q < 8; q++) j[q] = g_csrs[p + q];
        #pragma unroll
        for (int q = 0; q < 8; q++) u[q] = in2[j[q] * 32 + lane];
        #pragma unroll
        for (int q = 0; q < 8; q++) {
            float2 f0 = __half22float2(*(__half2*)&u[q].x);
            float2 f1 = __half22float2(*(__half2*)&u[q].y);
            acc.x += f0.x;
            acc.y += f0.y;
            acc.z += f1.x;
            acc.w += f1.y;
        }
    }
    for (; p < hi; p++) {
        int jj = g_csrs[p];
        uint2 u = in2[jj * 32 + lane];
        float2 f0 = __half22float2(*(__half2*)&u.x);
        float2 f1 = __half22float2(*(__half2*)&u.y);
        acc.x += f0.x;
        acc.y += f0.y;
        acc.z += f1.x;
        acc.w += f1.y;
    }
    uint2 us = in2[n * 32 + lane];
    float2 s0 = __half22float2(*(__half2*)&us.x);
    float2 s1 = __half22float2(*(__half2*)&us.y);
    float si = g_isqrt[n];
    float4 o;
    o.x = (acc.x + s0.x) * si;
    o.y = (acc.y + s0.y) * si;
    o.z = (acc.z + s1.x) * si;
    o.w = (acc.w + s1.y) * si;
    return o;
}

// ---------------- agg + relu epilogue: h = relu(agg(y1') + b1) -----------------
__global__ void k_aggrelu(const __half* __restrict__ in, const float* __restrict__ b,
                          __half* __restrict__ out) {
    int w = (blockIdx.x * blockDim.x + threadIdx.x) >> 5;
    int lane = threadIdx.x & 31;
    if (w >= NN) return;
    float4 o = agg_core((const uint2*)in, w, lane);
    float4 bv = ((const float4*)b)[lane];
    o.x = fmaxf(o.x + bv.x, 0.f);
    o.y = fmaxf(o.y + bv.y, 0.f);
    o.z = fmaxf(o.z + bv.z, 0.f);
    o.w = fmaxf(o.w + bv.w, 0.f);
    __half2 h0 = __floats2half2_rn(o.x, o.y);
    __half2 h1 = __floats2half2_rn(o.z, o.w);
    uint2 u;
    u.x = *(unsigned*)&h0;
    u.y = *(unsigned*)&h1;
    ((uint2*)out)[w * 32 + lane] = u;
}

// ---------------- agg + z epilogue: z = (aggmu+bmu) + noise*exp(aggls+bls) ----
__global__ void k_aggz(const __half* __restrict__ in, const float* __restrict__ bmu,
                       const float* __restrict__ bls, const float* __restrict__ noise) {
    int w = (blockIdx.x * blockDim.x + threadIdx.x) >> 5;
    int lane = threadIdx.x & 31;
    if (w >= NN) return;
    float4 o = agg_core((const uint2*)in, w, lane);

    float4 e = make_float4(0.f, 0.f, 0.f, 0.f);
    if (lane >= 16) {
        float4 bv = ((const float4*)bls)[lane - 16];
        float4 nv = ((const float4*)(noise + (size_t)w * 64))[lane - 16];
        e.x = expf(o.x + bv.x) * nv.x;
        e.y = expf(o.y + bv.y) * nv.y;
        e.z = expf(o.z + bv.z) * nv.z;
        e.w = expf(o.w + bv.w) * nv.w;
    }
    e.x = __shfl_down_sync(0xffffffffu, e.x, 16);
    e.y = __shfl_down_sync(0xffffffffu, e.y, 16);
    e.z = __shfl_down_sync(0xffffffffu, e.z, 16);
    e.w = __shfl_down_sync(0xffffffffu, e.w, 16);
    if (lane < 16) {
        float4 bv = ((const float4*)bmu)[lane];
        float zx = o.x + bv.x + e.x;
        float zy = o.y + bv.y + e.y;
        float zz = o.z + bv.z + e.z;
        float zw = o.w + bv.w + e.w;
        __half2 h0 = __floats2half2_rn(zx, zy);
        __half2 h1 = __floats2half2_rn(zz, zw);
        uint2 u;
        u.x = *(unsigned*)&h0;
        u.y = *(unsigned*)&h1;
        ((uint2*)g_zh)[w * 16 + lane] = u;
    }
}

// ---------------- decoder (CSR-ordered, software-pipelined) --------------------
__global__ void k_dec(float* __restrict__ out) {
    int gid = blockIdx.x * blockDim.x + threadIdx.x;
    if (gid < NN) g_cnt[gid] = 0;            // re-zero for next replay
    if (gid < NB) g_blkflag[gid] = 0;        // re-arm the chained scan
    int n = gid >> 5;
    if (n >= NN) return;
    int lane = threadIdx.x & 31;
    int g = lane >> 3, sl = lane & 7;
    unsigned gm = 0xffu << (g * 8);

    int lo = g_offs[n], hi = g_offs[n + 1];
    uint4 zd = ((const uint4*)g_zh)[n * 8 + sl];
    float2 d0 = __half22float2(*(__half2*)&zd.x);
    float2 d1 = __half22float2(*(__half2*)&zd.y);
    float2 d2 = __half22float2(*(__half2*)&zd.z);
    float2 d3 = __half22float2(*(__half2*)&zd.w);

    int p = lo + g;
    bool have = p < hi;
    int eid = 0;
    uint4 za = make_uint4(0u, 0u, 0u, 0u);
    if (have) {
        int s = g_csrs[p];
        eid = g_csre[p];
        za = ((const uint4*)g_zh)[s * 8 + sl];
    }
    while (have) {
        int p2 = p + 4;
        bool haveN = p2 < hi;
        int eidN = 0;
        uint4 zaN = make_uint4(0u, 0u, 0u, 0u);
        if (haveN) {
            int sN = g_csrs[p2];
            eidN = g_csre[p2];
            zaN = ((const uint4*)g_zh)[sN * 8 + sl];
        }
        float2 a0 = __half22float2(*(__half2*)&za.x);
        float2 a1 = __half22float2(*(__half2*)&za.y);
        float2 a2 = __half22float2(*(__half2*)&za.z);
        float2 a3 = __half22float2(*(__half2*)&za.w);
        float v = a0.x * d0.x + a0.y * d0.y + a1.x * d1.x + a1.y * d1.y
                + a2.x * d2.x + a2.y * d2.y + a3.x * d3.x + a3.y * d3.y;
        v += __shfl_xor_sync(gm, v, 4);
        v += __shfl_xor_sync(gm, v, 2);
        v += __shfl_xor_sync(gm, v, 1);
        if (sl == 0) out[eid] = v;
        p = p2; za = zaN; eid = eidN; have = haveN;
    }
}

// ---------------- launch -------------------------------------------------------
extern "C" void kernel_launch(void* const* d_in, const int* in_sizes, int n_in,
                              void* d_out, int out_size) {
    const int*   fidx  = (const int*)d_in[0];
    const int*   foff  = (const int*)d_in[1];
    const float* fw    = (const float*)d_in[2];
    const int*   edge  = (const int*)d_in[3];
    const float* noise = (const float*)d_in[4];
    const float* emb   = (const float*)d_in[5];
    const float* W1    = (const float*)d_in[6];
    const float* b1    = (const float*)d_in[7];
    const float* Wmu   = (const float*)d_in[8];
    const float* bmu   = (const float*)d_in[9];
    const float* Wls   = (const float*)d_in[10];
    const float* bls   = (const float*)d_in[11];
    float* out = (float*)d_out;

    const int* src = edge;
    const int* dst = edge + EE;

    __half *pxh = nullptr, *py = nullptr, *phh = nullptr, *pw1 = nullptr, *pwab = nullptr;
    cudaGetSymbolAddress((void**)&pxh, g_xh);
    cudaGetSymbolAddress((void**)&py, g_y);
    cudaGetSymbolAddress((void**)&phh, g_hh);
    cudaGetSymbolAddress((void**)&pw1, g_w1h);
    cudaGetSymbolAddress((void**)&pwab, g_wabh);

    static cudaStream_t s2 = nullptr;
    static cudaEvent_t evF = nullptr, evS = nullptr, evJ = nullptr;
    static bool ok = false;
    if (!s2) {
        ok = (cudaStreamCreateWithFlags(&s2, cudaStreamNonBlocking) == cudaSuccess) &&
             (cudaEventCreateWithFlags(&evF, cudaEventDisableTiming) == cudaSuccess) &&
             (cudaEventCreateWithFlags(&evS, cudaEventDisableTiming) == cudaSuccess) &&
             (cudaEventCreateWithFlags(&evJ, cudaEventDisableTiming) == cudaSuccess);
    }

    if (!ok) {
        k_hist<<<(EE / 8 + 255) / 256, 256>>>(dst);
        k_scan<<<NB, 1024>>>();
        k_scatter<<<(EE / 4 + 255) / 256, 256>>>(src, dst);
        k_cvt<<<(2 * DD * DD + 255) / 256, 256>>>(W1, Wmu, Wls);
        k_embed<<<(NN + 3) / 4, 128>>>(fidx, foff, fw, emb);
        k_gemmA<<<(NN + 63) / 64, 256>>>(pxh, pw1, py);
        k_aggrelu<<<(NN + 3) / 4, 128>>>(py, b1, phh);
        k_gemmA<<<(NN + 63) / 64, 256>>>(phh, pwab, py);
        k_aggz<<<(NN + 3) / 4, 128>>>(py, bmu, bls, noise);
        k_dec<<<(NN * 32 + 255) / 256, 256>>>(out);
        return;
    }

    // fork
    cudaEventRecord(evF, 0);
    cudaStreamWaitEvent(s2, evF, 0);

    // branch B (s2): weights + embedding (no CSR dependence)
    k_cvt<<<(2 * DD * DD + 255) / 256, 256, 0, s2>>>(W1, Wmu, Wls);
    k_embed<<<(NN + 3) / 4, 128, 0, s2>>>(fidx, foff, fw, emb);

    // branch A (default): hist + scan (produces isqrt), then scatter
    k_hist<<<(EE / 8 + 255) / 256, 256>>>(dst);
    k_scan<<<NB, 1024>>>();
    cudaEventRecord(evS, 0);                 // isqrt ready
    k_scatter<<<(EE / 4 + 255) / 256, 256>>>(src, dst);

    // branch B continues: gemm1' needs isqrt (prescaled epilogue)
    cudaStreamWaitEvent(s2, evS, 0);
    k_gemmA<<<(NN + 63) / 64, 256, 0, s2>>>(pxh, pw1, py);   // y1' = isqrt*(x@W1)
    cudaEventRecord(evJ, s2);

    // join, then the serial back half
    cudaStreamWaitEvent(0, evJ, 0);
    k_aggrelu<<<(NN + 3) / 4, 128>>>(py, b1, phh);           // h = relu(agg(y1')+b1)
    k_gemmA<<<(NN + 63) / 64, 256>>>(phh, pwab, py);         // y2' = isqrt*(h@[Wmu|Wls])
    k_aggz<<<(NN + 3) / 4, 128>>>(py, bmu, bls, noise);      // z
    k_dec<<<(NN * 32 + 255) / 256, 256>>>(out);
}